// round 12
// baseline (speedup 1.0000x reference)
#include <cuda_runtime.h>
#include <cuda_fp16.h>
#include <cuda_bf16.h>
#include <math_constants.h>

// ---------------------------------------------------------------------------
// SwinV2 block: window cosine-attention + res-post-norm MLP
// b=2, H=W=192, C=128, WS=16, NH=8, d=16
// GEMMs + attention on fp16 tensor cores, fp32 accumulate.
// GEMMs use BK=128 (whole K staged once) -> one sync, long MMA bursts.
// ---------------------------------------------------------------------------

#define M_TOK   73728
#define C_DIM   128
#define NH      8
#define HD      16
#define NWIN    288
#define NTOK    256
#define IMG     192
#define WPR     12
#define LOG2E   1.4426950408889634f

typedef unsigned int u32;

__device__ __half g_qkvh [ (size_t)M_TOK * 384 ];
__device__ uint2  g_biasF[ (size_t)NH * 16 * 32 * 32 ];
__device__ __half g_attnh[ (size_t)M_TOK * C_DIM ];
__device__ float  g_x1   [ (size_t)M_TOK * C_DIM ];
__device__ __half g_hidh [ (size_t)M_TOK * 256 ];

#define MMA16816(d0,d1,d2,d3,a0,a1,a2,a3,b0,b1)                          \
    asm volatile(                                                        \
        "mma.sync.aligned.m16n8k16.row.col.f32.f16.f16.f32 "             \
        "{%0,%1,%2,%3}, {%4,%5,%6,%7}, {%8,%9}, {%0,%1,%2,%3};"          \
        : "+f"(d0), "+f"(d1), "+f"(d2), "+f"(d3)                         \
        : "r"(a0), "r"(a1), "r"(a2), "r"(a3), "r"(b0), "r"(b1))

__device__ __forceinline__ float ex2(float x)
{
    float r;
    asm("ex2.approx.f32 %0, %1;" : "=f"(r) : "f"(x));
    return r;
}

// ---------------------------------------------------------------------------
// fp16 tensor-core GEMM, BK=128. Dynamic smem: As[128][136] + Bs[128][136]
// = 69632 bytes. 8 warps (2m x 4n), warp tile 64x32, 128 MMAs per k-chunk
// with a single __syncthreads between staging and compute.
// act: 0 = none, 1 = exact GELU, 2 = fused res + LayerNorm (N==128, C fp32).
// ---------------------------------------------------------------------------
#define GSM_BYTES (2 * 128 * 136 * 2)

template<bool A_HALF, bool C_HALF, int ACT>
__global__ __launch_bounds__(256) void hgemm_kernel(
    const void* __restrict__ Av, const float* __restrict__ B,
    const float* __restrict__ bias, void* __restrict__ Cv,
    int M, int N, int K,
    const float* __restrict__ res,
    const float* __restrict__ lnw, const float* __restrict__ lnb)
{
    extern __shared__ char dynsm[];
    __half (*As)[136] = reinterpret_cast<__half(*)[136]>(dynsm);
    __half (*Bs)[136] = reinterpret_cast<__half(*)[136]>(dynsm + 128 * 136 * 2);
    float2 (*red)[4]  = reinterpret_cast<float2(*)[4]>(dynsm);  // aliases As

    const float*  Af = (const float*)Av;
    const __half* Ah = (const __half*)Av;
    float*  Cf = (float*)Cv;
    __half* Ch = (__half*)Cv;

    const int tid  = threadIdx.x;
    const int lane = tid & 31;
    const int wid  = tid >> 5;
    const int warp_m = wid >> 2;
    const int warp_n = wid & 3;
    const int brow = blockIdx.y * 128;
    const int bcol = blockIdx.x * 128;

    const u32 a_smem = (u32)__cvta_generic_to_shared(&As[0][0]);
    const u32 b_smem = (u32)__cvta_generic_to_shared(&Bs[0][0]);

    float acc[4][4][4];
    #pragma unroll
    for (int mi = 0; mi < 4; mi++)
        #pragma unroll
        for (int ni = 0; ni < 4; ni++)
            #pragma unroll
            for (int z = 0; z < 4; z++) acc[mi][ni][z] = 0.f;

    // staging index decompositions
    const int ar  = tid >> 2;           // fp32 A / B row base (0..63, +64)
    const int ac  = (tid & 3) << 5;     // 32-col group
    const int arh = tid >> 1;           // fp16 A row (0..127)
    const int ach = (tid & 1) << 6;     // 64-col group

    for (int kt = 0; kt < K; kt += 128) {
        if (kt) __syncthreads();   // previous chunk's reads done

        // ---- stage A chunk (rows brow..+128, cols kt..+128)
        if (A_HALF) {
            const __half* src = Ah + (size_t)(brow + arh) * K + kt + ach;
            #pragma unroll
            for (int i = 0; i < 8; i++)
                *reinterpret_cast<uint4*>(&As[arh][ach + i * 8]) =
                    *reinterpret_cast<const uint4*>(src + i * 8);
        } else {
            #pragma unroll
            for (int h = 0; h < 2; h++) {
                const int r = ar + h * 64;
                const float* src = Af + (size_t)(brow + r) * K + kt + ac;
                #pragma unroll
                for (int i = 0; i < 8; i++) {
                    float4 v = *reinterpret_cast<const float4*>(src + i * 4);
                    *reinterpret_cast<__half2*>(&As[r][ac + i * 4]) =
                        __float22half2_rn(make_float2(v.x, v.y));
                    *reinterpret_cast<__half2*>(&As[r][ac + i * 4 + 2]) =
                        __float22half2_rn(make_float2(v.z, v.w));
                }
            }
        }
        // ---- stage B chunk (rows kt..+128, cols bcol..+128)
        #pragma unroll
        for (int h = 0; h < 2; h++) {
            const int r = ar + h * 64;
            const float* src = B + (size_t)(kt + r) * N + bcol + ac;
            #pragma unroll
            for (int i = 0; i < 8; i++) {
                float4 v = *reinterpret_cast<const float4*>(src + i * 4);
                *reinterpret_cast<__half2*>(&Bs[r][ac + i * 4]) =
                    __float22half2_rn(make_float2(v.x, v.y));
                *reinterpret_cast<__half2*>(&Bs[r][ac + i * 4 + 2]) =
                    __float22half2_rn(make_float2(v.z, v.w));
            }
        }
        __syncthreads();

        // ---- 8 k-steps of MMAs, no intervening syncs
        #pragma unroll
        for (int ks = 0; ks < 128; ks += 16) {
            u32 af[4][4];
            #pragma unroll
            for (int mi = 0; mi < 4; mi++) {
                int r = warp_m * 64 + mi * 16 + (lane & 15);
                int c = ks + ((lane >> 4) << 3);
                u32 addr = a_smem + (u32)(r * 136 + c) * 2u;
                asm volatile(
                    "ldmatrix.sync.aligned.m8n8.x4.shared.b16 {%0,%1,%2,%3}, [%4];"
                    : "=r"(af[mi][0]), "=r"(af[mi][1]), "=r"(af[mi][2]), "=r"(af[mi][3])
                    : "r"(addr));
            }
            u32 bf[4][2];
            #pragma unroll
            for (int p = 0; p < 2; p++) {
                int r = ks + (lane & 15);
                int c = warp_n * 32 + p * 16 + ((lane >> 4) << 3);
                u32 addr = b_smem + (u32)(r * 136 + c) * 2u;
                asm volatile(
                    "ldmatrix.sync.aligned.m8n8.x4.trans.shared.b16 {%0,%1,%2,%3}, [%4];"
                    : "=r"(bf[2*p][0]), "=r"(bf[2*p][1]),
                      "=r"(bf[2*p+1][0]), "=r"(bf[2*p+1][1])
                    : "r"(addr));
            }
            #pragma unroll
            for (int mi = 0; mi < 4; mi++)
                #pragma unroll
                for (int ni = 0; ni < 4; ni++) {
                    MMA16816(acc[mi][ni][0], acc[mi][ni][1],
                             acc[mi][ni][2], acc[mi][ni][3],
                             af[mi][0], af[mi][1], af[mi][2], af[mi][3],
                             bf[ni][0], bf[ni][1]);
                }
        }
    }

    const int g = lane >> 2;
    const int t = lane & 3;

    if (ACT == 2) {
        __syncthreads();   // all warps done reading As before red aliases it
        #pragma unroll
        for (int mi = 0; mi < 4; mi++) {
            #pragma unroll
            for (int ni = 0; ni < 4; ni++) {
                const int c = warp_n * 32 + ni * 8 + (t << 1);
                float2 bb = *reinterpret_cast<const float2*>(&bias[c]);
                acc[mi][ni][0] += bb.x; acc[mi][ni][1] += bb.y;
                acc[mi][ni][2] += bb.x; acc[mi][ni][3] += bb.y;
            }
            float s0 = 0.f, q0 = 0.f, s1 = 0.f, q1 = 0.f;
            #pragma unroll
            for (int ni = 0; ni < 4; ni++) {
                s0 += acc[mi][ni][0] + acc[mi][ni][1];
                q0 += acc[mi][ni][0]*acc[mi][ni][0] + acc[mi][ni][1]*acc[mi][ni][1];
                s1 += acc[mi][ni][2] + acc[mi][ni][3];
                q1 += acc[mi][ni][2]*acc[mi][ni][2] + acc[mi][ni][3]*acc[mi][ni][3];
            }
            s0 += __shfl_xor_sync(0xffffffffu, s0, 1);
            s0 += __shfl_xor_sync(0xffffffffu, s0, 2);
            q0 += __shfl_xor_sync(0xffffffffu, q0, 1);
            q0 += __shfl_xor_sync(0xffffffffu, q0, 2);
            s1 += __shfl_xor_sync(0xffffffffu, s1, 1);
            s1 += __shfl_xor_sync(0xffffffffu, s1, 2);
            q1 += __shfl_xor_sync(0xffffffffu, q1, 1);
            q1 += __shfl_xor_sync(0xffffffffu, q1, 2);
            if (t == 0) {
                const int rl = warp_m * 64 + mi * 16 + g;
                red[rl][warp_n]     = make_float2(s0, q0);
                red[rl + 8][warp_n] = make_float2(s1, q1);
            }
        }
        __syncthreads();

        #pragma unroll
        for (int mi = 0; mi < 4; mi++) {
            const int rl0 = warp_m * 64 + mi * 16 + g;
            const int rl1 = rl0 + 8;
            float2 p;
            float s0 = 0.f, q0 = 0.f, s1 = 0.f, q1 = 0.f;
            #pragma unroll
            for (int w = 0; w < 4; w++) {
                p = red[rl0][w]; s0 += p.x; q0 += p.y;
                p = red[rl1][w]; s1 += p.x; q1 += p.y;
            }
            const float mu0 = s0 * (1.f/128.f);
            const float mu1 = s1 * (1.f/128.f);
            const float rs0 = rsqrtf(q0 * (1.f/128.f) - mu0*mu0 + 1e-5f);
            const float rs1 = rsqrtf(q1 * (1.f/128.f) - mu1*mu1 + 1e-5f);

            const size_t gr0 = (size_t)(brow + rl0) * 128;
            const size_t gr1 = (size_t)(brow + rl1) * 128;
            #pragma unroll
            for (int ni = 0; ni < 4; ni++) {
                const int c = warp_n * 32 + ni * 8 + (t << 1);
                float2 wv = *reinterpret_cast<const float2*>(&lnw[c]);
                float2 bv = *reinterpret_cast<const float2*>(&lnb[c]);
                float2 r0v = *reinterpret_cast<const float2*>(&res[gr0 + c]);
                float2 r1v = *reinterpret_cast<const float2*>(&res[gr1 + c]);
                float2 o0, o1;
                o0.x = r0v.x + (acc[mi][ni][0] - mu0) * rs0 * wv.x + bv.x;
                o0.y = r0v.y + (acc[mi][ni][1] - mu0) * rs0 * wv.y + bv.y;
                o1.x = r1v.x + (acc[mi][ni][2] - mu1) * rs1 * wv.x + bv.x;
                o1.y = r1v.y + (acc[mi][ni][3] - mu1) * rs1 * wv.y + bv.y;
                *reinterpret_cast<float2*>(&Cf[gr0 + c]) = o0;
                *reinterpret_cast<float2*>(&Cf[gr1 + c]) = o1;
            }
        }
        return;
    }

    #pragma unroll
    for (int mi = 0; mi < 4; mi++) {
        #pragma unroll
        for (int ni = 0; ni < 4; ni++) {
            const int r0 = brow + warp_m * 64 + mi * 16 + g;
            const int c  = bcol + warp_n * 32 + ni * 8 + (t << 1);
            float2 bb = *reinterpret_cast<const float2*>(&bias[c]);
            float2 v0, v1;
            v0.x = acc[mi][ni][0] + bb.x; v0.y = acc[mi][ni][1] + bb.y;
            v1.x = acc[mi][ni][2] + bb.x; v1.y = acc[mi][ni][3] + bb.y;
            if (ACT == 1) {
                v0.x *= normcdff(v0.x); v0.y *= normcdff(v0.y);
                v1.x *= normcdff(v1.x); v1.y *= normcdff(v1.y);
            }
            if (C_HALF) {
                *reinterpret_cast<__half2*>(&Ch[(size_t)r0 * N + c]) =
                    __float22half2_rn(v0);
                *reinterpret_cast<__half2*>(&Ch[(size_t)(r0 + 8) * N + c]) =
                    __float22half2_rn(v1);
            } else {
                *reinterpret_cast<float2*>(&Cf[(size_t)r0 * N + c])       = v0;
                *reinterpret_cast<float2*>(&Cf[(size_t)(r0 + 8) * N + c]) = v1;
            }
        }
    }
}

// ---------------------------------------------------------------------------
// Bias in mma C-fragment layout, pre-multiplied by log2(e).
// ---------------------------------------------------------------------------
__global__ void biasf_kernel(const int* __restrict__ rpi,
                             const float* __restrict__ table,
                             uint2* __restrict__ biasF)
{
    const int qb = blockIdx.x >> 5;
    const int jt = blockIdx.x & 31;
    const int hd = blockIdx.y;
    const int lane = threadIdx.x;
    const int g = lane >> 2, t = lane & 3;
    const int i0 = qb * 16, j0 = jt * 8;

    float b00 = table[rpi[(i0 + g)     * NTOK + j0 + 2*t    ] * NH + hd] * LOG2E;
    float b01 = table[rpi[(i0 + g)     * NTOK + j0 + 2*t + 1] * NH + hd] * LOG2E;
    float b10 = table[rpi[(i0 + g + 8) * NTOK + j0 + 2*t    ] * NH + hd] * LOG2E;
    float b11 = table[rpi[(i0 + g + 8) * NTOK + j0 + 2*t + 1] * NH + hd] * LOG2E;

    uint2 r;
    *reinterpret_cast<__half2*>(&r.x) = __floats2half2_rn(b00, b01);
    *reinterpret_cast<__half2*>(&r.y) = __floats2half2_rn(b10, b11);
    biasF[((size_t)(hd * 16 + qb) * 32 + jt) * 32 + lane] = r;
}

// ---------------------------------------------------------------------------
// Tensor-core window attention (unchanged from round 11).
// ---------------------------------------------------------------------------
#define SKH  0
#define SKL  (256*24)
#define SVTH (2*256*24)
#define ATTN_SMEM_HALFS (2*256*24 + 16*264)

__global__ __launch_bounds__(128, 6) void attn_tc_kernel(
    const __half* __restrict__ qkv, const uint2* __restrict__ biasF,
    const float* __restrict__ logit_scale, __half* __restrict__ attn_out)
{
    __shared__ __half sm[ATTN_SMEM_HALFS];

    const int wi = blockIdx.x;
    const int hd = blockIdx.y;
    const int tid = threadIdx.x;

    const int bimg = wi / 144;
    const int wrem = wi % 144;
    const int wr = wrem / WPR, wc = wrem % WPR;
    const int rowbase = bimg * (IMG * IMG) + (wr * 16) * IMG + wc * 16;

    const float scale = __expf(fminf(logit_scale[hd], 4.6051702f));
    const float qmul  = scale * LOG2E;

    for (int tok = tid; tok < NTOK; tok += 128) {
        const int m = rowbase + (tok >> 4) * IMG + (tok & 15);
        const __half* base = qkv + (size_t)m * 384 + hd * HD;

        uint4 kraw0 = *reinterpret_cast<const uint4*>(base + 128);
        uint4 kraw1 = *reinterpret_cast<const uint4*>(base + 136);
        uint4 vraw0 = *reinterpret_cast<const uint4*>(base + 256);
        uint4 vraw1 = *reinterpret_cast<const uint4*>(base + 264);

        float kf[16];
        {
            const __half2* k2a = reinterpret_cast<const __half2*>(&kraw0);
            const __half2* k2b = reinterpret_cast<const __half2*>(&kraw1);
            #pragma unroll
            for (int z = 0; z < 4; z++) {
                float2 f = __half22float2(k2a[z]);
                kf[2*z] = f.x; kf[2*z+1] = f.y;
                f = __half22float2(k2b[z]);
                kf[8+2*z] = f.x; kf[8+2*z+1] = f.y;
            }
        }
        float ks = 0.f;
        #pragma unroll
        for (int z = 0; z < 16; z++) ks += kf[z] * kf[z];
        const float kr = 1.f / fmaxf(sqrtf(ks), 1e-12f);
        #pragma unroll
        for (int z = 0; z < 16; z++) {
            float kv = kf[z] * kr;
            __half kh = __float2half_rn(kv);
            sm[SKH + tok*24 + z] = kh;
            sm[SKL + tok*24 + z] = __float2half_rn(kv - __half2float(kh));
        }
        const __half* vh = reinterpret_cast<const __half*>(&vraw0);
        #pragma unroll
        for (int z = 0; z < 8; z++) sm[SVTH + z*264 + tok] = vh[z];
        vh = reinterpret_cast<const __half*>(&vraw1);
        #pragma unroll
        for (int z = 0; z < 8; z++) sm[SVTH + (8+z)*264 + tok] = vh[z];
    }
    __syncthreads();

    const int warp = tid >> 5;
    const int lane = tid & 31;
    const int g = lane >> 2;
    const int t = lane & 3;

    for (int qi = 0; qi < 4; qi++) {
        const int qb = warp * 4 + qi;
        const int i0 = qb * 16;
        const int r0 = i0 + g, r1 = i0 + g + 8;
        const int m0 = rowbase + (r0 >> 4) * IMG + (r0 & 15);
        const int m1 = rowbase + (r1 >> 4) * IMG + (r1 & 15);

        const __half* q0p = qkv + (size_t)m0 * 384 + hd * HD;
        const __half* q1p = qkv + (size_t)m1 * 384 + hd * HD;
        float2 a00 = __half22float2(*reinterpret_cast<const __half2*>(q0p + 2*t));
        float2 a01 = __half22float2(*reinterpret_cast<const __half2*>(q0p + 2*t + 8));
        float2 a10 = __half22float2(*reinterpret_cast<const __half2*>(q1p + 2*t));
        float2 a11 = __half22float2(*reinterpret_cast<const __half2*>(q1p + 2*t + 8));

        float s0 = a00.x*a00.x + a00.y*a00.y + a01.x*a01.x + a01.y*a01.y;
        float s1 = a10.x*a10.x + a10.y*a10.y + a11.x*a11.x + a11.y*a11.y;
        s0 += __shfl_xor_sync(0xffffffffu, s0, 1);
        s0 += __shfl_xor_sync(0xffffffffu, s0, 2);
        s1 += __shfl_xor_sync(0xffffffffu, s1, 1);
        s1 += __shfl_xor_sync(0xffffffffu, s1, 2);
        const float qr0 = qmul / fmaxf(sqrtf(s0), 1e-12f);
        const float qr1 = qmul / fmaxf(sqrtf(s1), 1e-12f);

        u32 qa[4];
        {
            __half2 h;
            h = __floats2half2_rn(a00.x * qr0, a00.y * qr0); qa[0] = *reinterpret_cast<u32*>(&h);
            h = __floats2half2_rn(a10.x * qr1, a10.y * qr1); qa[1] = *reinterpret_cast<u32*>(&h);
            h = __floats2half2_rn(a01.x * qr0, a01.y * qr0); qa[2] = *reinterpret_cast<u32*>(&h);
            h = __floats2half2_rn(a11.x * qr1, a11.y * qr1); qa[3] = *reinterpret_cast<u32*>(&h);
        }

        float o0[4] = {0.f,0.f,0.f,0.f};
        float o1[4] = {0.f,0.f,0.f,0.f};
        float l0 = 0.f, l1 = 0.f;

        const uint2* bp = biasF + ((size_t)(hd * 16 + qb) * 32) * 32 + lane;

        #pragma unroll 2
        for (int jp = 0; jp < 16; jp++) {
            const int j0a = (2 * jp) * 8;
            const int j0b = (2 * jp + 1) * 8;
            uint2 bb0 = __ldg(&bp[(2 * jp) * 32]);
            uint2 bb1 = __ldg(&bp[(2 * jp + 1) * 32]);

            u32 kh0 = *reinterpret_cast<u32*>(&sm[SKH + (j0a+g)*24 + 2*t]);
            u32 kh1 = *reinterpret_cast<u32*>(&sm[SKH + (j0a+g)*24 + 2*t + 8]);
            u32 kl0 = *reinterpret_cast<u32*>(&sm[SKL + (j0a+g)*24 + 2*t]);
            u32 kl1 = *reinterpret_cast<u32*>(&sm[SKL + (j0a+g)*24 + 2*t + 8]);
            float sa0 = 0.f, sa1 = 0.f, sa2 = 0.f, sa3 = 0.f;
            MMA16816(sa0,sa1,sa2,sa3, qa[0],qa[1],qa[2],qa[3], kh0,kh1);
            MMA16816(sa0,sa1,sa2,sa3, qa[0],qa[1],qa[2],qa[3], kl0,kl1);

            u32 mh0 = *reinterpret_cast<u32*>(&sm[SKH + (j0b+g)*24 + 2*t]);
            u32 mh1 = *reinterpret_cast<u32*>(&sm[SKH + (j0b+g)*24 + 2*t + 8]);
            u32 ml0 = *reinterpret_cast<u32*>(&sm[SKL + (j0b+g)*24 + 2*t]);
            u32 ml1 = *reinterpret_cast<u32*>(&sm[SKL + (j0b+g)*24 + 2*t + 8]);
            float sb0 = 0.f, sb1 = 0.f, sb2 = 0.f, sb3 = 0.f;
            MMA16816(sb0,sb1,sb2,sb3, qa[0],qa[1],qa[2],qa[3], mh0,mh1);
            MMA16816(sb0,sb1,sb2,sb3, qa[0],qa[1],qa[2],qa[3], ml0,ml1);

            float2 blo0 = __half22float2(*reinterpret_cast<__half2*>(&bb0.x));
            float2 bhi0 = __half22float2(*reinterpret_cast<__half2*>(&bb0.y));
            float2 blo1 = __half22float2(*reinterpret_cast<__half2*>(&bb1.x));
            float2 bhi1 = __half22float2(*reinterpret_cast<__half2*>(&bb1.y));

            float p0 = ex2(sa0 + blo0.x);
            float p1 = ex2(sa1 + blo0.y);
            float p2 = ex2(sa2 + bhi0.x);
            float p3 = ex2(sa3 + bhi0.y);
            float p4 = ex2(sb0 + blo1.x);
            float p5 = ex2(sb1 + blo1.y);
            float p6 = ex2(sb2 + bhi1.x);
            float p7 = ex2(sb3 + bhi1.y);
            l0 += p0 + p1 + p4 + p5;
            l1 += p2 + p3 + p6 + p7;

            __half2 h;
            u32 pa0, pa1, pa2, pa3;
            h = __floats2half2_rn(p0, p1); pa0 = *reinterpret_cast<u32*>(&h);
            h = __floats2half2_rn(p2, p3); pa1 = *reinterpret_cast<u32*>(&h);
            h = __floats2half2_rn(p4, p5); pa2 = *reinterpret_cast<u32*>(&h);
            h = __floats2half2_rn(p6, p7); pa3 = *reinterpret_cast<u32*>(&h);

            const int jb = jp * 16;
            u32 vh0 = *reinterpret_cast<u32*>(&sm[SVTH + g*264 + jb + 2*t]);
            u32 vh1 = *reinterpret_cast<u32*>(&sm[SVTH + g*264 + jb + 2*t + 8]);
            MMA16816(o0[0],o0[1],o0[2],o0[3], pa0,pa1,pa2,pa3, vh0,vh1);
            u32 wh0 = *reinterpret_cast<u32*>(&sm[SVTH + (8+g)*264 + jb + 2*t]);
            u32 wh1 = *reinterpret_cast<u32*>(&sm[SVTH + (8+g)*264 + jb + 2*t + 8]);
            MMA16816(o1[0],o1[1],o1[2],o1[3], pa0,pa1,pa2,pa3, wh0,wh1);
        }

        l0 += __shfl_xor_sync(0xffffffffu, l0, 1);
        l0 += __shfl_xor_sync(0xffffffffu, l0, 2);
        l1 += __shfl_xor_sync(0xffffffffu, l1, 1);
        l1 += __shfl_xor_sync(0xffffffffu, l1, 2);
        const float inv0 = 1.f / l0, inv1 = 1.f / l1;

        const int col = hd * HD + 2 * t;
        *reinterpret_cast<__half2*>(&attn_out[(size_t)m0 * C_DIM + col]) =
            __floats2half2_rn(o0[0] * inv0, o0[1] * inv0);
        *reinterpret_cast<__half2*>(&attn_out[(size_t)m1 * C_DIM + col]) =
            __floats2half2_rn(o0[2] * inv1, o0[3] * inv1);
        *reinterpret_cast<__half2*>(&attn_out[(size_t)m0 * C_DIM + col + 8]) =
            __floats2half2_rn(o1[0] * inv0, o1[1] * inv0);
        *reinterpret_cast<__half2*>(&attn_out[(size_t)m1 * C_DIM + col + 8]) =
            __floats2half2_rn(o1[2] * inv1, o1[3] * inv1);
    }
}

// ---------------------------------------------------------------------------
extern "C" void kernel_launch(void* const* d_in, const int* in_sizes, int n_in,
                              void* d_out, int out_size)
{
    const float* x           = (const float*)d_in[0];
    const float* qkv_w       = (const float*)d_in[1];
    const float* qkv_b       = (const float*)d_in[2];
    const float* proj_w      = (const float*)d_in[3];
    const float* proj_b      = (const float*)d_in[4];
    const float* logit_scale = (const float*)d_in[5];
    const float* rpb_table   = (const float*)d_in[6];
    const float* n1w         = (const float*)d_in[7];
    const float* n1b         = (const float*)d_in[8];
    const float* n2w         = (const float*)d_in[9];
    const float* n2b         = (const float*)d_in[10];
    const float* fc1_w       = (const float*)d_in[11];
    const float* fc1_b       = (const float*)d_in[12];
    const float* fc2_w       = (const float*)d_in[13];
    const float* fc2_b       = (const float*)d_in[14];
    const int*   rpi         = (const int*)d_in[17];
    float* out = (float*)d_out;

    float *p_x1;
    __half *p_qkvh, *p_attnh, *p_hidh;
    uint2 *p_biasF;
    cudaGetSymbolAddress((void**)&p_qkvh,  g_qkvh);
    cudaGetSymbolAddress((void**)&p_biasF, g_biasF);
    cudaGetSymbolAddress((void**)&p_attnh, g_attnh);
    cudaGetSymbolAddress((void**)&p_x1,    g_x1);
    cudaGetSymbolAddress((void**)&p_hidh,  g_hidh);

    static bool attr_done = false;
    if (!attr_done) {
        cudaFuncSetAttribute(hgemm_kernel<false,true,0>,
                             cudaFuncAttributeMaxDynamicSharedMemorySize, GSM_BYTES);
        cudaFuncSetAttribute(hgemm_kernel<true,false,2>,
                             cudaFuncAttributeMaxDynamicSharedMemorySize, GSM_BYTES);
        cudaFuncSetAttribute(hgemm_kernel<false,true,1>,
                             cudaFuncAttributeMaxDynamicSharedMemorySize, GSM_BYTES);
        attr_done = true;
    }

    // 1) bias fragments (pre-scaled by log2e)
    biasf_kernel<<<dim3(16 * 32, NH), 32>>>(rpi, rpb_table, p_biasF);

    // 2) QKV: fp32 A, fp16 C
    hgemm_kernel<false,true,0><<<dim3(384/128, M_TOK/128), 256, GSM_BYTES>>>(
        x, qkv_w, qkv_b, p_qkvh, M_TOK, 384, 128, nullptr, nullptr, nullptr);

    // 3) tensor-core window attention (fp16 in/out)
    attn_tc_kernel<<<dim3(NWIN, NH), 128>>>(p_qkvh, p_biasF, logit_scale, p_attnh);

    // 4) proj + fused LN + residual: x1 = x + LN(attn @ proj_w + proj_b)
    hgemm_kernel<true,false,2><<<dim3(1, M_TOK/128), 256, GSM_BYTES>>>(
        p_attnh, proj_w, proj_b, p_x1, M_TOK, 128, 128, x, n1w, n1b);

    // 5) fc1 + GELU: fp32 A, fp16 C
    hgemm_kernel<false,true,1><<<dim3(256/128, M_TOK/128), 256, GSM_BYTES>>>(
        p_x1, fc1_w, fc1_b, p_hidh, M_TOK, 256, 128, nullptr, nullptr, nullptr);

    // 6) fc2 + fused LN + residual: out = x1 + LN(hid @ fc2_w + fc2_b)
    hgemm_kernel<true,false,2><<<dim3(1, M_TOK/128), 256, GSM_BYTES>>>(
        p_hidh, fc2_w, fc2_b, out, M_TOK, 128, 256, p_x1, n2w, n2b);
}

// round 13
// speedup vs baseline: 1.3952x; 1.3952x over previous
#include <cuda_runtime.h>
#include <cuda_fp16.h>
#include <cuda_bf16.h>
#include <math_constants.h>

// ---------------------------------------------------------------------------
// SwinV2 block: window cosine-attention + res-post-norm MLP
// b=2, H=W=192, C=128, WS=16, NH=8, d=16
// All GEMM operands fp16 (weights/x pre-converted once). BK=32 reg-prefetch.
// Attention: query-block pairing shares k/v smem reads across 2 query tiles.
// ---------------------------------------------------------------------------

#define M_TOK   73728
#define C_DIM   128
#define NH      8
#define HD      16
#define NWIN    288
#define NTOK    256
#define IMG     192
#define WPR     12
#define LOG2E   1.4426950408889634f

typedef unsigned int u32;

__device__ __half g_xh   [ (size_t)M_TOK * C_DIM ];
__device__ __half g_wq   [ 128 * 384 ];
__device__ __half g_wp   [ 128 * 128 ];
__device__ __half g_w1   [ 128 * 256 ];
__device__ __half g_w2   [ 256 * 128 ];
__device__ __half g_qkvh [ (size_t)M_TOK * 384 ];
__device__ uint2  g_biasF[ (size_t)NH * 16 * 32 * 32 ];
__device__ __half g_attnh[ (size_t)M_TOK * C_DIM ];
__device__ float  g_x1   [ (size_t)M_TOK * C_DIM ];
__device__ __half g_x1h  [ (size_t)M_TOK * C_DIM ];
__device__ __half g_hidh [ (size_t)M_TOK * 256 ];

#define MMA16816(d0,d1,d2,d3,a0,a1,a2,a3,b0,b1)                          \
    asm volatile(                                                        \
        "mma.sync.aligned.m16n8k16.row.col.f32.f16.f16.f32 "             \
        "{%0,%1,%2,%3}, {%4,%5,%6,%7}, {%8,%9}, {%0,%1,%2,%3};"          \
        : "+f"(d0), "+f"(d1), "+f"(d2), "+f"(d3)                         \
        : "r"(a0), "r"(a1), "r"(a2), "r"(a3), "r"(b0), "r"(b1))

__device__ __forceinline__ float ex2(float x)
{
    float r;
    asm("ex2.approx.f32 %0, %1;" : "=f"(r) : "f"(x));
    return r;
}

// ---------------------------------------------------------------------------
// fp32 -> fp16 conversion for 5 segments (weights + x). 8 elems per thread.
// ---------------------------------------------------------------------------
__global__ void f2h_kernel(
    const float* __restrict__ s0, __half* __restrict__ d0, int n0,
    const float* __restrict__ s1, __half* __restrict__ d1, int n1,
    const float* __restrict__ s2, __half* __restrict__ d2, int n2,
    const float* __restrict__ s3, __half* __restrict__ d3, int n3,
    const float* __restrict__ s4, __half* __restrict__ d4, int n4)
{
    const int seg = blockIdx.y;
    const float* s; __half* d; int n;
    switch (seg) {
        case 0: s = s0; d = d0; n = n0; break;
        case 1: s = s1; d = d1; n = n1; break;
        case 2: s = s2; d = d2; n = n2; break;
        case 3: s = s3; d = d3; n = n3; break;
        default: s = s4; d = d4; n = n4; break;
    }
    int idx = (blockIdx.x * blockDim.x + threadIdx.x) * 8;
    if (idx >= n) return;
    float4 a = *reinterpret_cast<const float4*>(s + idx);
    float4 b = *reinterpret_cast<const float4*>(s + idx + 4);
    uint2 o;
    *reinterpret_cast<__half2*>(&o.x) = __float22half2_rn(make_float2(a.x, a.y));
    *reinterpret_cast<__half2*>(&o.y) = __float22half2_rn(make_float2(a.z, a.w));
    *reinterpret_cast<uint2*>(d + idx) = o;
    *reinterpret_cast<__half2*>(&o.x) = __float22half2_rn(make_float2(b.x, b.y));
    *reinterpret_cast<__half2*>(&o.y) = __float22half2_rn(make_float2(b.z, b.w));
    *reinterpret_cast<uint2*>(d + idx + 4) = o;
}

// ---------------------------------------------------------------------------
// fp16 tensor-core GEMM, all operands fp16, BK=32 with register prefetch.
// act: 0 none, 1 exact GELU, 2 fused res + LayerNorm (N==128; C fp32 + C16).
// Tile 128x128, 8 warps (2m x 4n), warp tile 64x32.
// ---------------------------------------------------------------------------
template<bool C_HALF, int ACT>
__global__ __launch_bounds__(256) void hgemm_kernel(
    const __half* __restrict__ A, const __half* __restrict__ B,
    const float* __restrict__ bias, void* __restrict__ Cv,
    int M, int N, int K,
    const float* __restrict__ res,
    const float* __restrict__ lnw, const float* __restrict__ lnb,
    __half* __restrict__ C16)
{
    __shared__ __half As[128][40];
    __shared__ __half Bs[32][136];
    __shared__ float2 red[128][4];

    float*  Cf = (float*)Cv;
    __half* Ch = (__half*)Cv;

    const int tid  = threadIdx.x;
    const int lane = tid & 31;
    const int wid  = tid >> 5;
    const int warp_m = wid >> 2;
    const int warp_n = wid & 3;
    const int brow = blockIdx.y * 128;
    const int bcol = blockIdx.x * 128;

    const int a_r = tid >> 2;            // +64
    const int a_c = (tid & 3) << 3;
    const int b_r = tid >> 4;            // +16
    const int b_c = (tid & 15) << 3;

    const u32 a_smem = (u32)__cvta_generic_to_shared(&As[0][0]);
    const u32 b_smem = (u32)__cvta_generic_to_shared(&Bs[0][0]);

    float acc[4][4][4];
    #pragma unroll
    for (int mi = 0; mi < 4; mi++)
        #pragma unroll
        for (int ni = 0; ni < 4; ni++)
            #pragma unroll
            for (int z = 0; z < 4; z++) acc[mi][ni][z] = 0.f;

    uint4 a_pf[2], b_pf[2];
    #pragma unroll
    for (int t = 0; t < 2; t++) {
        a_pf[t] = *reinterpret_cast<const uint4*>(
            &A[(size_t)(brow + a_r + t * 64) * K + a_c]);
        b_pf[t] = *reinterpret_cast<const uint4*>(
            &B[(size_t)(b_r + t * 16) * N + bcol + b_c]);
    }

    for (int kt = 0; kt < K; kt += 32) {
        #pragma unroll
        for (int t = 0; t < 2; t++) {
            *reinterpret_cast<uint4*>(&As[a_r + t * 64][a_c]) = a_pf[t];
            *reinterpret_cast<uint4*>(&Bs[b_r + t * 16][b_c]) = b_pf[t];
        }
        __syncthreads();

        if (kt + 32 < K) {
            #pragma unroll
            for (int t = 0; t < 2; t++) {
                a_pf[t] = *reinterpret_cast<const uint4*>(
                    &A[(size_t)(brow + a_r + t * 64) * K + kt + 32 + a_c]);
                b_pf[t] = *reinterpret_cast<const uint4*>(
                    &B[(size_t)(kt + 32 + b_r + t * 16) * N + bcol + b_c]);
            }
        }

        #pragma unroll
        for (int ks = 0; ks < 32; ks += 16) {
            u32 af[4][4];
            #pragma unroll
            for (int mi = 0; mi < 4; mi++) {
                int r = warp_m * 64 + mi * 16 + (lane & 15);
                int c = ks + ((lane >> 4) << 3);
                u32 addr = a_smem + (u32)(r * 40 + c) * 2u;
                asm volatile(
                    "ldmatrix.sync.aligned.m8n8.x4.shared.b16 {%0,%1,%2,%3}, [%4];"
                    : "=r"(af[mi][0]), "=r"(af[mi][1]), "=r"(af[mi][2]), "=r"(af[mi][3])
                    : "r"(addr));
            }
            u32 bf[4][2];
            #pragma unroll
            for (int p = 0; p < 2; p++) {
                int r = ks + (lane & 15);
                int c = warp_n * 32 + p * 16 + ((lane >> 4) << 3);
                u32 addr = b_smem + (u32)(r * 136 + c) * 2u;
                asm volatile(
                    "ldmatrix.sync.aligned.m8n8.x4.trans.shared.b16 {%0,%1,%2,%3}, [%4];"
                    : "=r"(bf[2*p][0]), "=r"(bf[2*p][1]),
                      "=r"(bf[2*p+1][0]), "=r"(bf[2*p+1][1])
                    : "r"(addr));
            }
            #pragma unroll
            for (int mi = 0; mi < 4; mi++)
                #pragma unroll
                for (int ni = 0; ni < 4; ni++) {
                    MMA16816(acc[mi][ni][0], acc[mi][ni][1],
                             acc[mi][ni][2], acc[mi][ni][3],
                             af[mi][0], af[mi][1], af[mi][2], af[mi][3],
                             bf[ni][0], bf[ni][1]);
                }
        }
        __syncthreads();
    }

    const int g = lane >> 2;
    const int t = lane & 3;

    if (ACT == 2) {
        // fused bias + LayerNorm + residual (N == 128), plus fp16 copy
        #pragma unroll
        for (int mi = 0; mi < 4; mi++) {
            #pragma unroll
            for (int ni = 0; ni < 4; ni++) {
                const int c = warp_n * 32 + ni * 8 + (t << 1);
                float2 bb = *reinterpret_cast<const float2*>(&bias[c]);
                acc[mi][ni][0] += bb.x; acc[mi][ni][1] += bb.y;
                acc[mi][ni][2] += bb.x; acc[mi][ni][3] += bb.y;
            }
            float s0 = 0.f, q0 = 0.f, s1 = 0.f, q1 = 0.f;
            #pragma unroll
            for (int ni = 0; ni < 4; ni++) {
                s0 += acc[mi][ni][0] + acc[mi][ni][1];
                q0 += acc[mi][ni][0]*acc[mi][ni][0] + acc[mi][ni][1]*acc[mi][ni][1];
                s1 += acc[mi][ni][2] + acc[mi][ni][3];
                q1 += acc[mi][ni][2]*acc[mi][ni][2] + acc[mi][ni][3]*acc[mi][ni][3];
            }
            s0 += __shfl_xor_sync(0xffffffffu, s0, 1);
            s0 += __shfl_xor_sync(0xffffffffu, s0, 2);
            q0 += __shfl_xor_sync(0xffffffffu, q0, 1);
            q0 += __shfl_xor_sync(0xffffffffu, q0, 2);
            s1 += __shfl_xor_sync(0xffffffffu, s1, 1);
            s1 += __shfl_xor_sync(0xffffffffu, s1, 2);
            q1 += __shfl_xor_sync(0xffffffffu, q1, 1);
            q1 += __shfl_xor_sync(0xffffffffu, q1, 2);
            if (t == 0) {
                const int rl = warp_m * 64 + mi * 16 + g;
                red[rl][warp_n]     = make_float2(s0, q0);
                red[rl + 8][warp_n] = make_float2(s1, q1);
            }
        }
        __syncthreads();

        #pragma unroll
        for (int mi = 0; mi < 4; mi++) {
            const int rl0 = warp_m * 64 + mi * 16 + g;
            const int rl1 = rl0 + 8;
            float2 p;
            float s0 = 0.f, q0 = 0.f, s1 = 0.f, q1 = 0.f;
            #pragma unroll
            for (int w = 0; w < 4; w++) {
                p = red[rl0][w]; s0 += p.x; q0 += p.y;
                p = red[rl1][w]; s1 += p.x; q1 += p.y;
            }
            const float mu0 = s0 * (1.f/128.f);
            const float mu1 = s1 * (1.f/128.f);
            const float rs0 = rsqrtf(q0 * (1.f/128.f) - mu0*mu0 + 1e-5f);
            const float rs1 = rsqrtf(q1 * (1.f/128.f) - mu1*mu1 + 1e-5f);

            const size_t gr0 = (size_t)(brow + rl0) * 128;
            const size_t gr1 = (size_t)(brow + rl1) * 128;
            #pragma unroll
            for (int ni = 0; ni < 4; ni++) {
                const int c = warp_n * 32 + ni * 8 + (t << 1);
                float2 wv = *reinterpret_cast<const float2*>(&lnw[c]);
                float2 bv = *reinterpret_cast<const float2*>(&lnb[c]);
                float2 r0v = *reinterpret_cast<const float2*>(&res[gr0 + c]);
                float2 r1v = *reinterpret_cast<const float2*>(&res[gr1 + c]);
                float2 o0, o1;
                o0.x = r0v.x + (acc[mi][ni][0] - mu0) * rs0 * wv.x + bv.x;
                o0.y = r0v.y + (acc[mi][ni][1] - mu0) * rs0 * wv.y + bv.y;
                o1.x = r1v.x + (acc[mi][ni][2] - mu1) * rs1 * wv.x + bv.x;
                o1.y = r1v.y + (acc[mi][ni][3] - mu1) * rs1 * wv.y + bv.y;
                *reinterpret_cast<float2*>(&Cf[gr0 + c]) = o0;
                *reinterpret_cast<float2*>(&Cf[gr1 + c]) = o1;
                if (C16) {
                    *reinterpret_cast<__half2*>(&C16[gr0 + c]) = __float22half2_rn(o0);
                    *reinterpret_cast<__half2*>(&C16[gr1 + c]) = __float22half2_rn(o1);
                }
            }
        }
        return;
    }

    #pragma unroll
    for (int mi = 0; mi < 4; mi++) {
        #pragma unroll
        for (int ni = 0; ni < 4; ni++) {
            const int r0 = brow + warp_m * 64 + mi * 16 + g;
            const int c  = bcol + warp_n * 32 + ni * 8 + (t << 1);
            float2 bb = *reinterpret_cast<const float2*>(&bias[c]);
            float2 v0, v1;
            v0.x = acc[mi][ni][0] + bb.x; v0.y = acc[mi][ni][1] + bb.y;
            v1.x = acc[mi][ni][2] + bb.x; v1.y = acc[mi][ni][3] + bb.y;
            if (ACT == 1) {
                v0.x *= normcdff(v0.x); v0.y *= normcdff(v0.y);
                v1.x *= normcdff(v1.x); v1.y *= normcdff(v1.y);
            }
            if (C_HALF) {
                *reinterpret_cast<__half2*>(&Ch[(size_t)r0 * N + c]) =
                    __float22half2_rn(v0);
                *reinterpret_cast<__half2*>(&Ch[(size_t)(r0 + 8) * N + c]) =
                    __float22half2_rn(v1);
            } else {
                *reinterpret_cast<float2*>(&Cf[(size_t)r0 * N + c])       = v0;
                *reinterpret_cast<float2*>(&Cf[(size_t)(r0 + 8) * N + c]) = v1;
            }
        }
    }
}

// ---------------------------------------------------------------------------
// Bias in mma C-fragment layout, pre-multiplied by log2(e).
// ---------------------------------------------------------------------------
__global__ void biasf_kernel(const int* __restrict__ rpi,
                             const float* __restrict__ table,
                             uint2* __restrict__ biasF)
{
    const int qb = blockIdx.x >> 5;
    const int jt = blockIdx.x & 31;
    const int hd = blockIdx.y;
    const int lane = threadIdx.x;
    const int g = lane >> 2, t = lane & 3;
    const int i0 = qb * 16, j0 = jt * 8;

    float b00 = table[rpi[(i0 + g)     * NTOK + j0 + 2*t    ] * NH + hd] * LOG2E;
    float b01 = table[rpi[(i0 + g)     * NTOK + j0 + 2*t + 1] * NH + hd] * LOG2E;
    float b10 = table[rpi[(i0 + g + 8) * NTOK + j0 + 2*t    ] * NH + hd] * LOG2E;
    float b11 = table[rpi[(i0 + g + 8) * NTOK + j0 + 2*t + 1] * NH + hd] * LOG2E;

    uint2 r;
    *reinterpret_cast<__half2*>(&r.x) = __floats2half2_rn(b00, b01);
    *reinterpret_cast<__half2*>(&r.y) = __floats2half2_rn(b10, b11);
    biasF[((size_t)(hd * 16 + qb) * 32 + jt) * 32 + lane] = r;
}

// ---------------------------------------------------------------------------
// Tensor-core window attention with query-block PAIRING: each warp iterates
// 2 pairs of query blocks; inside the key loop the k/v smem reads are shared
// between the 2 query blocks (half the LDS, double the independent chains).
// Math per query block identical to round 11.
// ---------------------------------------------------------------------------
#define SKH  0
#define SKL  (256*24)
#define SVTH (2*256*24)
#define ATTN_SMEM_HALFS (2*256*24 + 16*264)

__global__ __launch_bounds__(128, 4) void attn_tc_kernel(
    const __half* __restrict__ qkv, const uint2* __restrict__ biasF,
    const float* __restrict__ logit_scale, __half* __restrict__ attn_out)
{
    __shared__ __half sm[ATTN_SMEM_HALFS];

    const int wi = blockIdx.x;
    const int hd = blockIdx.y;
    const int tid = threadIdx.x;

    const int bimg = wi / 144;
    const int wrem = wi % 144;
    const int wr = wrem / WPR, wc = wrem % WPR;
    const int rowbase = bimg * (IMG * IMG) + (wr * 16) * IMG + wc * 16;

    const float scale = __expf(fminf(logit_scale[hd], 4.6051702f));
    const float qmul  = scale * LOG2E;

    for (int tok = tid; tok < NTOK; tok += 128) {
        const int m = rowbase + (tok >> 4) * IMG + (tok & 15);
        const __half* base = qkv + (size_t)m * 384 + hd * HD;

        uint4 kraw0 = *reinterpret_cast<const uint4*>(base + 128);
        uint4 kraw1 = *reinterpret_cast<const uint4*>(base + 136);
        uint4 vraw0 = *reinterpret_cast<const uint4*>(base + 256);
        uint4 vraw1 = *reinterpret_cast<const uint4*>(base + 264);

        float kf[16];
        {
            const __half2* k2a = reinterpret_cast<const __half2*>(&kraw0);
            const __half2* k2b = reinterpret_cast<const __half2*>(&kraw1);
            #pragma unroll
            for (int z = 0; z < 4; z++) {
                float2 f = __half22float2(k2a[z]);
                kf[2*z] = f.x; kf[2*z+1] = f.y;
                f = __half22float2(k2b[z]);
                kf[8+2*z] = f.x; kf[8+2*z+1] = f.y;
            }
        }
        float ks = 0.f;
        #pragma unroll
        for (int z = 0; z < 16; z++) ks += kf[z] * kf[z];
        const float kr = 1.f / fmaxf(sqrtf(ks), 1e-12f);
        #pragma unroll
        for (int z = 0; z < 16; z++) {
            float kv = kf[z] * kr;
            __half kh = __float2half_rn(kv);
            sm[SKH + tok*24 + z] = kh;
            sm[SKL + tok*24 + z] = __float2half_rn(kv - __half2float(kh));
        }
        const __half* vh = reinterpret_cast<const __half*>(&vraw0);
        #pragma unroll
        for (int z = 0; z < 8; z++) sm[SVTH + z*264 + tok] = vh[z];
        vh = reinterpret_cast<const __half*>(&vraw1);
        #pragma unroll
        for (int z = 0; z < 8; z++) sm[SVTH + (8+z)*264 + tok] = vh[z];
    }
    __syncthreads();

    const int warp = tid >> 5;
    const int lane = tid & 31;
    const int g = lane >> 2;
    const int t = lane & 3;

    for (int qp = 0; qp < 2; qp++) {
        const int qbA = warp * 4 + qp * 2;
        const int qbB = qbA + 1;

        int mA0, mA1, mB0, mB1;
        u32 qaA[4], qaB[4];
        {
            // --- load + normalize q for both query blocks
            const int iA = qbA * 16, iB = qbB * 16;
            const int rA0 = iA + g, rA1 = iA + g + 8;
            const int rB0 = iB + g, rB1 = iB + g + 8;
            mA0 = rowbase + (rA0 >> 4) * IMG + (rA0 & 15);
            mA1 = rowbase + (rA1 >> 4) * IMG + (rA1 & 15);
            mB0 = rowbase + (rB0 >> 4) * IMG + (rB0 & 15);
            mB1 = rowbase + (rB1 >> 4) * IMG + (rB1 & 15);

            const __half* pA0 = qkv + (size_t)mA0 * 384 + hd * HD;
            const __half* pA1 = qkv + (size_t)mA1 * 384 + hd * HD;
            const __half* pB0 = qkv + (size_t)mB0 * 384 + hd * HD;
            const __half* pB1 = qkv + (size_t)mB1 * 384 + hd * HD;

            float2 aA00 = __half22float2(*reinterpret_cast<const __half2*>(pA0 + 2*t));
            float2 aA01 = __half22float2(*reinterpret_cast<const __half2*>(pA0 + 2*t + 8));
            float2 aA10 = __half22float2(*reinterpret_cast<const __half2*>(pA1 + 2*t));
            float2 aA11 = __half22float2(*reinterpret_cast<const __half2*>(pA1 + 2*t + 8));
            float2 aB00 = __half22float2(*reinterpret_cast<const __half2*>(pB0 + 2*t));
            float2 aB01 = __half22float2(*reinterpret_cast<const __half2*>(pB0 + 2*t + 8));
            float2 aB10 = __half22float2(*reinterpret_cast<const __half2*>(pB1 + 2*t));
            float2 aB11 = __half22float2(*reinterpret_cast<const __half2*>(pB1 + 2*t + 8));

            float sA0 = aA00.x*aA00.x + aA00.y*aA00.y + aA01.x*aA01.x + aA01.y*aA01.y;
            float sA1 = aA10.x*aA10.x + aA10.y*aA10.y + aA11.x*aA11.x + aA11.y*aA11.y;
            float sB0 = aB00.x*aB00.x + aB00.y*aB00.y + aB01.x*aB01.x + aB01.y*aB01.y;
            float sB1 = aB10.x*aB10.x + aB10.y*aB10.y + aB11.x*aB11.x + aB11.y*aB11.y;
            sA0 += __shfl_xor_sync(0xffffffffu, sA0, 1);
            sA0 += __shfl_xor_sync(0xffffffffu, sA0, 2);
            sA1 += __shfl_xor_sync(0xffffffffu, sA1, 1);
            sA1 += __shfl_xor_sync(0xffffffffu, sA1, 2);
            sB0 += __shfl_xor_sync(0xffffffffu, sB0, 1);
            sB0 += __shfl_xor_sync(0xffffffffu, sB0, 2);
            sB1 += __shfl_xor_sync(0xffffffffu, sB1, 1);
            sB1 += __shfl_xor_sync(0xffffffffu, sB1, 2);
            const float qrA0 = qmul / fmaxf(sqrtf(sA0), 1e-12f);
            const float qrA1 = qmul / fmaxf(sqrtf(sA1), 1e-12f);
            const float qrB0 = qmul / fmaxf(sqrtf(sB0), 1e-12f);
            const float qrB1 = qmul / fmaxf(sqrtf(sB1), 1e-12f);

            __half2 h;
            h = __floats2half2_rn(aA00.x * qrA0, aA00.y * qrA0); qaA[0] = *reinterpret_cast<u32*>(&h);
            h = __floats2half2_rn(aA10.x * qrA1, aA10.y * qrA1); qaA[1] = *reinterpret_cast<u32*>(&h);
            h = __floats2half2_rn(aA01.x * qrA0, aA01.y * qrA0); qaA[2] = *reinterpret_cast<u32*>(&h);
            h = __floats2half2_rn(aA11.x * qrA1, aA11.y * qrA1); qaA[3] = *reinterpret_cast<u32*>(&h);
            h = __floats2half2_rn(aB00.x * qrB0, aB00.y * qrB0); qaB[0] = *reinterpret_cast<u32*>(&h);
            h = __floats2half2_rn(aB10.x * qrB1, aB10.y * qrB1); qaB[1] = *reinterpret_cast<u32*>(&h);
            h = __floats2half2_rn(aB01.x * qrB0, aB01.y * qrB0); qaB[2] = *reinterpret_cast<u32*>(&h);
            h = __floats2half2_rn(aB11.x * qrB1, aB11.y * qrB1); qaB[3] = *reinterpret_cast<u32*>(&h);
        }

        float oA0[4] = {0,0,0,0}, oA1[4] = {0,0,0,0};
        float oB0[4] = {0,0,0,0}, oB1[4] = {0,0,0,0};
        float lA0 = 0.f, lA1 = 0.f, lB0 = 0.f, lB1 = 0.f;

        const uint2* bpA = biasF + ((size_t)(hd * 16 + qbA) * 32) * 32 + lane;
        const uint2* bpB = biasF + ((size_t)(hd * 16 + qbB) * 32) * 32 + lane;

        #pragma unroll 2
        for (int jp = 0; jp < 16; jp++) {
            const int j0a = (2 * jp) * 8;
            const int j0b = (2 * jp + 1) * 8;
            uint2 bA0 = __ldg(&bpA[(2 * jp) * 32]);
            uint2 bA1 = __ldg(&bpA[(2 * jp + 1) * 32]);
            uint2 bB0 = __ldg(&bpB[(2 * jp) * 32]);
            uint2 bB1 = __ldg(&bpB[(2 * jp + 1) * 32]);

            // shared k fragments (even, odd jtiles)
            u32 kh0 = *reinterpret_cast<u32*>(&sm[SKH + (j0a+g)*24 + 2*t]);
            u32 kh1 = *reinterpret_cast<u32*>(&sm[SKH + (j0a+g)*24 + 2*t + 8]);
            u32 kl0 = *reinterpret_cast<u32*>(&sm[SKL + (j0a+g)*24 + 2*t]);
            u32 kl1 = *reinterpret_cast<u32*>(&sm[SKL + (j0a+g)*24 + 2*t + 8]);
            u32 mh0 = *reinterpret_cast<u32*>(&sm[SKH + (j0b+g)*24 + 2*t]);
            u32 mh1 = *reinterpret_cast<u32*>(&sm[SKH + (j0b+g)*24 + 2*t + 8]);
            u32 ml0 = *reinterpret_cast<u32*>(&sm[SKL + (j0b+g)*24 + 2*t]);
            u32 ml1 = *reinterpret_cast<u32*>(&sm[SKL + (j0b+g)*24 + 2*t + 8]);

            // S for qbA
            float sAa0=0,sAa1=0,sAa2=0,sAa3=0, sAb0=0,sAb1=0,sAb2=0,sAb3=0;
            MMA16816(sAa0,sAa1,sAa2,sAa3, qaA[0],qaA[1],qaA[2],qaA[3], kh0,kh1);
            MMA16816(sAa0,sAa1,sAa2,sAa3, qaA[0],qaA[1],qaA[2],qaA[3], kl0,kl1);
            MMA16816(sAb0,sAb1,sAb2,sAb3, qaA[0],qaA[1],qaA[2],qaA[3], mh0,mh1);
            MMA16816(sAb0,sAb1,sAb2,sAb3, qaA[0],qaA[1],qaA[2],qaA[3], ml0,ml1);
            // S for qbB
            float sBa0=0,sBa1=0,sBa2=0,sBa3=0, sBb0=0,sBb1=0,sBb2=0,sBb3=0;
            MMA16816(sBa0,sBa1,sBa2,sBa3, qaB[0],qaB[1],qaB[2],qaB[3], kh0,kh1);
            MMA16816(sBa0,sBa1,sBa2,sBa3, qaB[0],qaB[1],qaB[2],qaB[3], kl0,kl1);
            MMA16816(sBb0,sBb1,sBb2,sBb3, qaB[0],qaB[1],qaB[2],qaB[3], mh0,mh1);
            MMA16816(sBb0,sBb1,sBb2,sBb3, qaB[0],qaB[1],qaB[2],qaB[3], ml0,ml1);

            float2 f;
            f = __half22float2(*reinterpret_cast<__half2*>(&bA0.x));
            float pA0 = ex2(sAa0 + f.x), pA1 = ex2(sAa1 + f.y);
            f = __half22float2(*reinterpret_cast<__half2*>(&bA0.y));
            float pA2 = ex2(sAa2 + f.x), pA3 = ex2(sAa3 + f.y);
            f = __half22float2(*reinterpret_cast<__half2*>(&bA1.x));
            float pA4 = ex2(sAb0 + f.x), pA5 = ex2(sAb1 + f.y);
            f = __half22float2(*reinterpret_cast<__half2*>(&bA1.y));
            float pA6 = ex2(sAb2 + f.x), pA7 = ex2(sAb3 + f.y);
            lA0 += pA0 + pA1 + pA4 + pA5;
            lA1 += pA2 + pA3 + pA6 + pA7;

            f = __half22float2(*reinterpret_cast<__half2*>(&bB0.x));
            float pB0 = ex2(sBa0 + f.x), pB1 = ex2(sBa1 + f.y);
            f = __half22float2(*reinterpret_cast<__half2*>(&bB0.y));
            float pB2 = ex2(sBa2 + f.x), pB3 = ex2(sBa3 + f.y);
            f = __half22float2(*reinterpret_cast<__half2*>(&bB1.x));
            float pB4 = ex2(sBb0 + f.x), pB5 = ex2(sBb1 + f.y);
            f = __half22float2(*reinterpret_cast<__half2*>(&bB1.y));
            float pB6 = ex2(sBb2 + f.x), pB7 = ex2(sBb3 + f.y);
            lB0 += pB0 + pB1 + pB4 + pB5;
            lB1 += pB2 + pB3 + pB6 + pB7;

            __half2 h;
            u32 aA0c, aA1c, aA2c, aA3c, aB0c, aB1c, aB2c, aB3c;
            h = __floats2half2_rn(pA0, pA1); aA0c = *reinterpret_cast<u32*>(&h);
            h = __floats2half2_rn(pA2, pA3); aA1c = *reinterpret_cast<u32*>(&h);
            h = __floats2half2_rn(pA4, pA5); aA2c = *reinterpret_cast<u32*>(&h);
            h = __floats2half2_rn(pA6, pA7); aA3c = *reinterpret_cast<u32*>(&h);
            h = __floats2half2_rn(pB0, pB1); aB0c = *reinterpret_cast<u32*>(&h);
            h = __floats2half2_rn(pB2, pB3); aB1c = *reinterpret_cast<u32*>(&h);
            h = __floats2half2_rn(pB4, pB5); aB2c = *reinterpret_cast<u32*>(&h);
            h = __floats2half2_rn(pB6, pB7); aB3c = *reinterpret_cast<u32*>(&h);

            const int jb = jp * 16;
            u32 vh0 = *reinterpret_cast<u32*>(&sm[SVTH + g*264 + jb + 2*t]);
            u32 vh1 = *reinterpret_cast<u32*>(&sm[SVTH + g*264 + jb + 2*t + 8]);
            u32 wh0 = *reinterpret_cast<u32*>(&sm[SVTH + (8+g)*264 + jb + 2*t]);
            u32 wh1 = *reinterpret_cast<u32*>(&sm[SVTH + (8+g)*264 + jb + 2*t + 8]);

            MMA16816(oA0[0],oA0[1],oA0[2],oA0[3], aA0c,aA1c,aA2c,aA3c, vh0,vh1);
            MMA16816(oA1[0],oA1[1],oA1[2],oA1[3], aA0c,aA1c,aA2c,aA3c, wh0,wh1);
            MMA16816(oB0[0],oB0[1],oB0[2],oB0[3], aB0c,aB1c,aB2c,aB3c, vh0,vh1);
            MMA16816(oB1[0],oB1[1],oB1[2],oB1[3], aB0c,aB1c,aB2c,aB3c, wh0,wh1);
        }

        // reductions + outputs for both query blocks
        lA0 += __shfl_xor_sync(0xffffffffu, lA0, 1);
        lA0 += __shfl_xor_sync(0xffffffffu, lA0, 2);
        lA1 += __shfl_xor_sync(0xffffffffu, lA1, 1);
        lA1 += __shfl_xor_sync(0xffffffffu, lA1, 2);
        lB0 += __shfl_xor_sync(0xffffffffu, lB0, 1);
        lB0 += __shfl_xor_sync(0xffffffffu, lB0, 2);
        lB1 += __shfl_xor_sync(0xffffffffu, lB1, 1);
        lB1 += __shfl_xor_sync(0xffffffffu, lB1, 2);
        const float iA0 = 1.f / lA0, iA1 = 1.f / lA1;
        const float iB0 = 1.f / lB0, iB1 = 1.f / lB1;

        const int col = hd * HD + 2 * t;
        *reinterpret_cast<__half2*>(&attn_out[(size_t)mA0 * C_DIM + col]) =
            __floats2half2_rn(oA0[0] * iA0, oA0[1] * iA0);
        *reinterpret_cast<__half2*>(&attn_out[(size_t)mA1 * C_DIM + col]) =
            __floats2half2_rn(oA0[2] * iA1, oA0[3] * iA1);
        *reinterpret_cast<__half2*>(&attn_out[(size_t)mA0 * C_DIM + col + 8]) =
            __floats2half2_rn(oA1[0] * iA0, oA1[1] * iA0);
        *reinterpret_cast<__half2*>(&attn_out[(size_t)mA1 * C_DIM + col + 8]) =
            __floats2half2_rn(oA1[2] * iA1, oA1[3] * iA1);
        *reinterpret_cast<__half2*>(&attn_out[(size_t)mB0 * C_DIM + col]) =
            __floats2half2_rn(oB0[0] * iB0, oB0[1] * iB0);
        *reinterpret_cast<__half2*>(&attn_out[(size_t)mB1 * C_DIM + col]) =
            __floats2half2_rn(oB0[2] * iB1, oB0[3] * iB1);
        *reinterpret_cast<__half2*>(&attn_out[(size_t)mB0 * C_DIM + col + 8]) =
            __floats2half2_rn(oB1[0] * iB0, oB1[1] * iB0);
        *reinterpret_cast<__half2*>(&attn_out[(size_t)mB1 * C_DIM + col + 8]) =
            __floats2half2_rn(oB1[2] * iB1, oB1[3] * iB1);
    }
}

// ---------------------------------------------------------------------------
extern "C" void kernel_launch(void* const* d_in, const int* in_sizes, int n_in,
                              void* d_out, int out_size)
{
    const float* x           = (const float*)d_in[0];
    const float* qkv_w       = (const float*)d_in[1];
    const float* qkv_b       = (const float*)d_in[2];
    const float* proj_w      = (const float*)d_in[3];
    const float* proj_b      = (const float*)d_in[4];
    const float* logit_scale = (const float*)d_in[5];
    const float* rpb_table   = (const float*)d_in[6];
    const float* n1w         = (const float*)d_in[7];
    const float* n1b         = (const float*)d_in[8];
    const float* n2w         = (const float*)d_in[9];
    const float* n2b         = (const float*)d_in[10];
    const float* fc1_w       = (const float*)d_in[11];
    const float* fc1_b       = (const float*)d_in[12];
    const float* fc2_w       = (const float*)d_in[13];
    const float* fc2_b       = (const float*)d_in[14];
    const int*   rpi         = (const int*)d_in[17];
    float* out = (float*)d_out;

    float *p_x1;
    __half *p_xh, *p_wq, *p_wp, *p_w1, *p_w2;
    __half *p_qkvh, *p_attnh, *p_x1h, *p_hidh;
    uint2 *p_biasF;
    cudaGetSymbolAddress((void**)&p_xh,    g_xh);
    cudaGetSymbolAddress((void**)&p_wq,    g_wq);
    cudaGetSymbolAddress((void**)&p_wp,    g_wp);
    cudaGetSymbolAddress((void**)&p_w1,    g_w1);
    cudaGetSymbolAddress((void**)&p_w2,    g_w2);
    cudaGetSymbolAddress((void**)&p_qkvh,  g_qkvh);
    cudaGetSymbolAddress((void**)&p_biasF, g_biasF);
    cudaGetSymbolAddress((void**)&p_attnh, g_attnh);
    cudaGetSymbolAddress((void**)&p_x1,    g_x1);
    cudaGetSymbolAddress((void**)&p_x1h,   g_x1h);
    cudaGetSymbolAddress((void**)&p_hidh,  g_hidh);

    // 0) convert x + all weights to fp16 (x is largest: 9.4M elems)
    {
        const int nx = M_TOK * C_DIM;
        const int bl = (nx + 2047) / 2048;
        f2h_kernel<<<dim3(bl, 5), 256>>>(
            x, p_xh, nx,
            qkv_w, p_wq, 128 * 384,
            proj_w, p_wp, 128 * 128,
            fc1_w, p_w1, 128 * 256,
            fc2_w, p_w2, 256 * 128);
    }

    // 1) bias fragments
    biasf_kernel<<<dim3(16 * 32, NH), 32>>>(rpi, rpb_table, p_biasF);

    // 2) QKV
    hgemm_kernel<true,0><<<dim3(384/128, M_TOK/128), 256>>>(
        p_xh, p_wq, qkv_b, p_qkvh, M_TOK, 384, 128,
        nullptr, nullptr, nullptr, nullptr);

    // 3) attention
    attn_tc_kernel<<<dim3(NWIN, NH), 128>>>(p_qkvh, p_biasF, logit_scale, p_attnh);

    // 4) proj + LN + residual (writes fp32 x1 and fp16 x1h)
    hgemm_kernel<false,2><<<dim3(1, M_TOK/128), 256>>>(
        p_attnh, p_wp, proj_b, p_x1, M_TOK, 128, 128,
        x, n1w, n1b, p_x1h);

    // 5) fc1 + GELU
    hgemm_kernel<true,1><<<dim3(256/128, M_TOK/128), 256>>>(
        p_x1h, p_w1, fc1_b, p_hidh, M_TOK, 256, 128,
        nullptr, nullptr, nullptr, nullptr);

    // 6) fc2 + LN + residual
    hgemm_kernel<false,2><<<dim3(1, M_TOK/128), 256>>>(
        p_hidh, p_w2, fc2_b, out, M_TOK, 128, 256,
        p_x1, n2w, n2b, nullptr);
}

// round 14
// speedup vs baseline: 1.5687x; 1.1243x over previous
#include <cuda_runtime.h>
#include <cuda_fp16.h>
#include <cuda_bf16.h>
#include <math_constants.h>

// ---------------------------------------------------------------------------
// SwinV2 block: window cosine-attention + res-post-norm MLP
// b=2, H=W=192, C=128, WS=16, NH=8, d=16
// R11 GEMM structure (BK=32, reg prefetch, fp32->fp16 staging conversion)
// + R13 paired attention (2 query blocks share k/v smem reads).
// ---------------------------------------------------------------------------

#define M_TOK   73728
#define C_DIM   128
#define NH      8
#define HD      16
#define NWIN    288
#define NTOK    256
#define IMG     192
#define WPR     12
#define LOG2E   1.4426950408889634f

typedef unsigned int u32;

__device__ __half g_qkvh [ (size_t)M_TOK * 384 ];
__device__ uint2  g_biasF[ (size_t)NH * 16 * 32 * 32 ];
__device__ __half g_attnh[ (size_t)M_TOK * C_DIM ];
__device__ float  g_x1   [ (size_t)M_TOK * C_DIM ];
__device__ __half g_hidh [ (size_t)M_TOK * 256 ];

#define MMA16816(d0,d1,d2,d3,a0,a1,a2,a3,b0,b1)                          \
    asm volatile(                                                        \
        "mma.sync.aligned.m16n8k16.row.col.f32.f16.f16.f32 "             \
        "{%0,%1,%2,%3}, {%4,%5,%6,%7}, {%8,%9}, {%0,%1,%2,%3};"          \
        : "+f"(d0), "+f"(d1), "+f"(d2), "+f"(d3)                         \
        : "r"(a0), "r"(a1), "r"(a2), "r"(a3), "r"(b0), "r"(b1))

__device__ __forceinline__ float ex2(float x)
{
    float r;
    asm("ex2.approx.f32 %0, %1;" : "=f"(r) : "f"(x));
    return r;
}

// ---------------------------------------------------------------------------
// fp16 tensor-core GEMM (R11 structure).
// act: 0 none, 1 exact GELU, 2 fused res + LayerNorm (N==128, C fp32).
// ---------------------------------------------------------------------------
template<bool A_HALF, bool C_HALF, int ACT>
__global__ __launch_bounds__(256) void hgemm_kernel(
    const void* __restrict__ Av, const float* __restrict__ B,
    const float* __restrict__ bias, void* __restrict__ Cv,
    int M, int N, int K,
    const float* __restrict__ res,
    const float* __restrict__ lnw, const float* __restrict__ lnb)
{
    __shared__ __half As[128][40];
    __shared__ __half Bs[32][136];
    __shared__ float2 red[128][4];

    const float*  Af = (const float*)Av;
    const __half* Ah = (const __half*)Av;
    float*  Cf = (float*)Cv;
    __half* Ch = (__half*)Cv;

    const int tid  = threadIdx.x;
    const int lane = tid & 31;
    const int wid  = tid >> 5;
    const int warp_m = wid >> 2;
    const int warp_n = wid & 3;
    const int brow = blockIdx.y * 128;
    const int bcol = blockIdx.x * 128;

    const int a_m0 = tid >> 3;
    const int a_k4 = (tid & 7) << 2;
    const int a_m0h = tid >> 2;
    const int a_k8  = (tid & 3) << 3;
    const int b_k0 = tid >> 5;
    const int b_n4 = (tid & 31) << 2;

    const u32 a_smem = (u32)__cvta_generic_to_shared(&As[0][0]);
    const u32 b_smem = (u32)__cvta_generic_to_shared(&Bs[0][0]);

    float acc[4][4][4];
    #pragma unroll
    for (int mi = 0; mi < 4; mi++)
        #pragma unroll
        for (int ni = 0; ni < 4; ni++)
            #pragma unroll
            for (int z = 0; z < 4; z++) acc[mi][ni][z] = 0.f;

    float4 a_pf[4];
    uint4  a_pfh[2];
    float4 b_pf[4];
    if (A_HALF) {
        #pragma unroll
        for (int t = 0; t < 2; t++)
            a_pfh[t] = *reinterpret_cast<const uint4*>(
                &Ah[(size_t)(brow + a_m0h + t * 64) * K + a_k8]);
    } else {
        #pragma unroll
        for (int t = 0; t < 4; t++)
            a_pf[t] = *reinterpret_cast<const float4*>(
                &Af[(size_t)(brow + a_m0 + t * 32) * K + a_k4]);
    }
    #pragma unroll
    for (int t = 0; t < 4; t++)
        b_pf[t] = *reinterpret_cast<const float4*>(
            &B[(size_t)(b_k0 + t * 8) * N + bcol + b_n4]);

    for (int kt = 0; kt < K; kt += 32) {
        if (A_HALF) {
            #pragma unroll
            for (int t = 0; t < 2; t++)
                *reinterpret_cast<uint4*>(&As[a_m0h + t * 64][a_k8]) = a_pfh[t];
        } else {
            #pragma unroll
            for (int t = 0; t < 4; t++) {
                __half2 h0 = __float22half2_rn(make_float2(a_pf[t].x, a_pf[t].y));
                __half2 h1 = __float22half2_rn(make_float2(a_pf[t].z, a_pf[t].w));
                *reinterpret_cast<__half2*>(&As[a_m0 + t * 32][a_k4 + 0]) = h0;
                *reinterpret_cast<__half2*>(&As[a_m0 + t * 32][a_k4 + 2]) = h1;
            }
        }
        #pragma unroll
        for (int t = 0; t < 4; t++) {
            __half2 g0 = __float22half2_rn(make_float2(b_pf[t].x, b_pf[t].y));
            __half2 g1 = __float22half2_rn(make_float2(b_pf[t].z, b_pf[t].w));
            *reinterpret_cast<__half2*>(&Bs[b_k0 + t * 8][b_n4 + 0]) = g0;
            *reinterpret_cast<__half2*>(&Bs[b_k0 + t * 8][b_n4 + 2]) = g1;
        }
        __syncthreads();

        if (kt + 32 < K) {
            if (A_HALF) {
                #pragma unroll
                for (int t = 0; t < 2; t++)
                    a_pfh[t] = *reinterpret_cast<const uint4*>(
                        &Ah[(size_t)(brow + a_m0h + t * 64) * K + kt + 32 + a_k8]);
            } else {
                #pragma unroll
                for (int t = 0; t < 4; t++)
                    a_pf[t] = *reinterpret_cast<const float4*>(
                        &Af[(size_t)(brow + a_m0 + t * 32) * K + kt + 32 + a_k4]);
            }
            #pragma unroll
            for (int t = 0; t < 4; t++)
                b_pf[t] = *reinterpret_cast<const float4*>(
                    &B[(size_t)(kt + 32 + b_k0 + t * 8) * N + bcol + b_n4]);
        }

        #pragma unroll
        for (int ks = 0; ks < 32; ks += 16) {
            u32 af[4][4];
            #pragma unroll
            for (int mi = 0; mi < 4; mi++) {
                int r = warp_m * 64 + mi * 16 + (lane & 15);
                int c = ks + ((lane >> 4) << 3);
                u32 addr = a_smem + (u32)(r * 40 + c) * 2u;
                asm volatile(
                    "ldmatrix.sync.aligned.m8n8.x4.shared.b16 {%0,%1,%2,%3}, [%4];"
                    : "=r"(af[mi][0]), "=r"(af[mi][1]), "=r"(af[mi][2]), "=r"(af[mi][3])
                    : "r"(addr));
            }
            u32 bf[4][2];
            #pragma unroll
            for (int p = 0; p < 2; p++) {
                int r = ks + (lane & 15);
                int c = warp_n * 32 + p * 16 + ((lane >> 4) << 3);
                u32 addr = b_smem + (u32)(r * 136 + c) * 2u;
                asm volatile(
                    "ldmatrix.sync.aligned.m8n8.x4.trans.shared.b16 {%0,%1,%2,%3}, [%4];"
                    : "=r"(bf[2*p][0]), "=r"(bf[2*p][1]),
                      "=r"(bf[2*p+1][0]), "=r"(bf[2*p+1][1])
                    : "r"(addr));
            }
            #pragma unroll
            for (int mi = 0; mi < 4; mi++)
                #pragma unroll
                for (int ni = 0; ni < 4; ni++) {
                    MMA16816(acc[mi][ni][0], acc[mi][ni][1],
                             acc[mi][ni][2], acc[mi][ni][3],
                             af[mi][0], af[mi][1], af[mi][2], af[mi][3],
                             bf[ni][0], bf[ni][1]);
                }
        }
        __syncthreads();
    }

    const int g = lane >> 2;
    const int t = lane & 3;

    if (ACT == 2) {
        #pragma unroll
        for (int mi = 0; mi < 4; mi++) {
            #pragma unroll
            for (int ni = 0; ni < 4; ni++) {
                const int c = warp_n * 32 + ni * 8 + (t << 1);
                float2 bb = *reinterpret_cast<const float2*>(&bias[c]);
                acc[mi][ni][0] += bb.x; acc[mi][ni][1] += bb.y;
                acc[mi][ni][2] += bb.x; acc[mi][ni][3] += bb.y;
            }
            float s0 = 0.f, q0 = 0.f, s1 = 0.f, q1 = 0.f;
            #pragma unroll
            for (int ni = 0; ni < 4; ni++) {
                s0 += acc[mi][ni][0] + acc[mi][ni][1];
                q0 += acc[mi][ni][0]*acc[mi][ni][0] + acc[mi][ni][1]*acc[mi][ni][1];
                s1 += acc[mi][ni][2] + acc[mi][ni][3];
                q1 += acc[mi][ni][2]*acc[mi][ni][2] + acc[mi][ni][3]*acc[mi][ni][3];
            }
            s0 += __shfl_xor_sync(0xffffffffu, s0, 1);
            s0 += __shfl_xor_sync(0xffffffffu, s0, 2);
            q0 += __shfl_xor_sync(0xffffffffu, q0, 1);
            q0 += __shfl_xor_sync(0xffffffffu, q0, 2);
            s1 += __shfl_xor_sync(0xffffffffu, s1, 1);
            s1 += __shfl_xor_sync(0xffffffffu, s1, 2);
            q1 += __shfl_xor_sync(0xffffffffu, q1, 1);
            q1 += __shfl_xor_sync(0xffffffffu, q1, 2);
            if (t == 0) {
                const int rl = warp_m * 64 + mi * 16 + g;
                red[rl][warp_n]     = make_float2(s0, q0);
                red[rl + 8][warp_n] = make_float2(s1, q1);
            }
        }
        __syncthreads();

        #pragma unroll
        for (int mi = 0; mi < 4; mi++) {
            const int rl0 = warp_m * 64 + mi * 16 + g;
            const int rl1 = rl0 + 8;
            float2 p;
            float s0 = 0.f, q0 = 0.f, s1 = 0.f, q1 = 0.f;
            #pragma unroll
            for (int w = 0; w < 4; w++) {
                p = red[rl0][w]; s0 += p.x; q0 += p.y;
                p = red[rl1][w]; s1 += p.x; q1 += p.y;
            }
            const float mu0 = s0 * (1.f/128.f);
            const float mu1 = s1 * (1.f/128.f);
            const float rs0 = rsqrtf(q0 * (1.f/128.f) - mu0*mu0 + 1e-5f);
            const float rs1 = rsqrtf(q1 * (1.f/128.f) - mu1*mu1 + 1e-5f);

            const size_t gr0 = (size_t)(brow + rl0) * 128;
            const size_t gr1 = (size_t)(brow + rl1) * 128;
            #pragma unroll
            for (int ni = 0; ni < 4; ni++) {
                const int c = warp_n * 32 + ni * 8 + (t << 1);
                float2 wv = *reinterpret_cast<const float2*>(&lnw[c]);
                float2 bv = *reinterpret_cast<const float2*>(&lnb[c]);
                float2 r0v = *reinterpret_cast<const float2*>(&res[gr0 + c]);
                float2 r1v = *reinterpret_cast<const float2*>(&res[gr1 + c]);
                float2 o0, o1;
                o0.x = r0v.x + (acc[mi][ni][0] - mu0) * rs0 * wv.x + bv.x;
                o0.y = r0v.y + (acc[mi][ni][1] - mu0) * rs0 * wv.y + bv.y;
                o1.x = r1v.x + (acc[mi][ni][2] - mu1) * rs1 * wv.x + bv.x;
                o1.y = r1v.y + (acc[mi][ni][3] - mu1) * rs1 * wv.y + bv.y;
                *reinterpret_cast<float2*>(&Cf[gr0 + c]) = o0;
                *reinterpret_cast<float2*>(&Cf[gr1 + c]) = o1;
            }
        }
        return;
    }

    #pragma unroll
    for (int mi = 0; mi < 4; mi++) {
        #pragma unroll
        for (int ni = 0; ni < 4; ni++) {
            const int r0 = brow + warp_m * 64 + mi * 16 + g;
            const int c  = bcol + warp_n * 32 + ni * 8 + (t << 1);
            float2 bb = *reinterpret_cast<const float2*>(&bias[c]);
            float2 v0, v1;
            v0.x = acc[mi][ni][0] + bb.x; v0.y = acc[mi][ni][1] + bb.y;
            v1.x = acc[mi][ni][2] + bb.x; v1.y = acc[mi][ni][3] + bb.y;
            if (ACT == 1) {
                v0.x *= normcdff(v0.x); v0.y *= normcdff(v0.y);
                v1.x *= normcdff(v1.x); v1.y *= normcdff(v1.y);
            }
            if (C_HALF) {
                *reinterpret_cast<__half2*>(&Ch[(size_t)r0 * N + c]) =
                    __float22half2_rn(v0);
                *reinterpret_cast<__half2*>(&Ch[(size_t)(r0 + 8) * N + c]) =
                    __float22half2_rn(v1);
            } else {
                *reinterpret_cast<float2*>(&Cf[(size_t)r0 * N + c])       = v0;
                *reinterpret_cast<float2*>(&Cf[(size_t)(r0 + 8) * N + c]) = v1;
            }
        }
    }
}

// ---------------------------------------------------------------------------
// Bias in mma C-fragment layout, pre-multiplied by log2(e).
// ---------------------------------------------------------------------------
__global__ void biasf_kernel(const int* __restrict__ rpi,
                             const float* __restrict__ table,
                             uint2* __restrict__ biasF)
{
    const int qb = blockIdx.x >> 5;
    const int jt = blockIdx.x & 31;
    const int hd = blockIdx.y;
    const int lane = threadIdx.x;
    const int g = lane >> 2, t = lane & 3;
    const int i0 = qb * 16, j0 = jt * 8;

    float b00 = table[rpi[(i0 + g)     * NTOK + j0 + 2*t    ] * NH + hd] * LOG2E;
    float b01 = table[rpi[(i0 + g)     * NTOK + j0 + 2*t + 1] * NH + hd] * LOG2E;
    float b10 = table[rpi[(i0 + g + 8) * NTOK + j0 + 2*t    ] * NH + hd] * LOG2E;
    float b11 = table[rpi[(i0 + g + 8) * NTOK + j0 + 2*t + 1] * NH + hd] * LOG2E;

    uint2 r;
    *reinterpret_cast<__half2*>(&r.x) = __floats2half2_rn(b00, b01);
    *reinterpret_cast<__half2*>(&r.y) = __floats2half2_rn(b10, b11);
    biasF[((size_t)(hd * 16 + qb) * 32 + jt) * 32 + lane] = r;
}

// ---------------------------------------------------------------------------
// Paired tensor-core window attention (R13, measured 84.6us).
// ---------------------------------------------------------------------------
#define SKH  0
#define SKL  (256*24)
#define SVTH (2*256*24)
#define ATTN_SMEM_HALFS (2*256*24 + 16*264)

__global__ __launch_bounds__(128, 4) void attn_tc_kernel(
    const __half* __restrict__ qkv, const uint2* __restrict__ biasF,
    const float* __restrict__ logit_scale, __half* __restrict__ attn_out)
{
    __shared__ __half sm[ATTN_SMEM_HALFS];

    const int wi = blockIdx.x;
    const int hd = blockIdx.y;
    const int tid = threadIdx.x;

    const int bimg = wi / 144;
    const int wrem = wi % 144;
    const int wr = wrem / WPR, wc = wrem % WPR;
    const int rowbase = bimg * (IMG * IMG) + (wr * 16) * IMG + wc * 16;

    const float scale = __expf(fminf(logit_scale[hd], 4.6051702f));
    const float qmul  = scale * LOG2E;

    for (int tok = tid; tok < NTOK; tok += 128) {
        const int m = rowbase + (tok >> 4) * IMG + (tok & 15);
        const __half* base = qkv + (size_t)m * 384 + hd * HD;

        uint4 kraw0 = *reinterpret_cast<const uint4*>(base + 128);
        uint4 kraw1 = *reinterpret_cast<const uint4*>(base + 136);
        uint4 vraw0 = *reinterpret_cast<const uint4*>(base + 256);
        uint4 vraw1 = *reinterpret_cast<const uint4*>(base + 264);

        float kf[16];
        {
            const __half2* k2a = reinterpret_cast<const __half2*>(&kraw0);
            const __half2* k2b = reinterpret_cast<const __half2*>(&kraw1);
            #pragma unroll
            for (int z = 0; z < 4; z++) {
                float2 f = __half22float2(k2a[z]);
                kf[2*z] = f.x; kf[2*z+1] = f.y;
                f = __half22float2(k2b[z]);
                kf[8+2*z] = f.x; kf[8+2*z+1] = f.y;
            }
        }
        float ks = 0.f;
        #pragma unroll
        for (int z = 0; z < 16; z++) ks += kf[z] * kf[z];
        const float kr = 1.f / fmaxf(sqrtf(ks), 1e-12f);
        #pragma unroll
        for (int z = 0; z < 16; z++) {
            float kv = kf[z] * kr;
            __half kh = __float2half_rn(kv);
            sm[SKH + tok*24 + z] = kh;
            sm[SKL + tok*24 + z] = __float2half_rn(kv - __half2float(kh));
        }
        const __half* vh = reinterpret_cast<const __half*>(&vraw0);
        #pragma unroll
        for (int z = 0; z < 8; z++) sm[SVTH + z*264 + tok] = vh[z];
        vh = reinterpret_cast<const __half*>(&vraw1);
        #pragma unroll
        for (int z = 0; z < 8; z++) sm[SVTH + (8+z)*264 + tok] = vh[z];
    }
    __syncthreads();

    const int warp = tid >> 5;
    const int lane = tid & 31;
    const int g = lane >> 2;
    const int t = lane & 3;

    for (int qp = 0; qp < 2; qp++) {
        const int qbA = warp * 4 + qp * 2;
        const int qbB = qbA + 1;

        int mA0, mA1, mB0, mB1;
        u32 qaA[4], qaB[4];
        {
            const int iA = qbA * 16, iB = qbB * 16;
            const int rA0 = iA + g, rA1 = iA + g + 8;
            const int rB0 = iB + g, rB1 = iB + g + 8;
            mA0 = rowbase + (rA0 >> 4) * IMG + (rA0 & 15);
            mA1 = rowbase + (rA1 >> 4) * IMG + (rA1 & 15);
            mB0 = rowbase + (rB0 >> 4) * IMG + (rB0 & 15);
            mB1 = rowbase + (rB1 >> 4) * IMG + (rB1 & 15);

            const __half* pA0 = qkv + (size_t)mA0 * 384 + hd * HD;
            const __half* pA1 = qkv + (size_t)mA1 * 384 + hd * HD;
            const __half* pB0 = qkv + (size_t)mB0 * 384 + hd * HD;
            const __half* pB1 = qkv + (size_t)mB1 * 384 + hd * HD;

            float2 aA00 = __half22float2(*reinterpret_cast<const __half2*>(pA0 + 2*t));
            float2 aA01 = __half22float2(*reinterpret_cast<const __half2*>(pA0 + 2*t + 8));
            float2 aA10 = __half22float2(*reinterpret_cast<const __half2*>(pA1 + 2*t));
            float2 aA11 = __half22float2(*reinterpret_cast<const __half2*>(pA1 + 2*t + 8));
            float2 aB00 = __half22float2(*reinterpret_cast<const __half2*>(pB0 + 2*t));
            float2 aB01 = __half22float2(*reinterpret_cast<const __half2*>(pB0 + 2*t + 8));
            float2 aB10 = __half22float2(*reinterpret_cast<const __half2*>(pB1 + 2*t));
            float2 aB11 = __half22float2(*reinterpret_cast<const __half2*>(pB1 + 2*t + 8));

            float sA0 = aA00.x*aA00.x + aA00.y*aA00.y + aA01.x*aA01.x + aA01.y*aA01.y;
            float sA1 = aA10.x*aA10.x + aA10.y*aA10.y + aA11.x*aA11.x + aA11.y*aA11.y;
            float sB0 = aB00.x*aB00.x + aB00.y*aB00.y + aB01.x*aB01.x + aB01.y*aB01.y;
            float sB1 = aB10.x*aB10.x + aB10.y*aB10.y + aB11.x*aB11.x + aB11.y*aB11.y;
            sA0 += __shfl_xor_sync(0xffffffffu, sA0, 1);
            sA0 += __shfl_xor_sync(0xffffffffu, sA0, 2);
            sA1 += __shfl_xor_sync(0xffffffffu, sA1, 1);
            sA1 += __shfl_xor_sync(0xffffffffu, sA1, 2);
            sB0 += __shfl_xor_sync(0xffffffffu, sB0, 1);
            sB0 += __shfl_xor_sync(0xffffffffu, sB0, 2);
            sB1 += __shfl_xor_sync(0xffffffffu, sB1, 1);
            sB1 += __shfl_xor_sync(0xffffffffu, sB1, 2);
            const float qrA0 = qmul / fmaxf(sqrtf(sA0), 1e-12f);
            const float qrA1 = qmul / fmaxf(sqrtf(sA1), 1e-12f);
            const float qrB0 = qmul / fmaxf(sqrtf(sB0), 1e-12f);
            const float qrB1 = qmul / fmaxf(sqrtf(sB1), 1e-12f);

            __half2 h;
            h = __floats2half2_rn(aA00.x * qrA0, aA00.y * qrA0); qaA[0] = *reinterpret_cast<u32*>(&h);
            h = __floats2half2_rn(aA10.x * qrA1, aA10.y * qrA1); qaA[1] = *reinterpret_cast<u32*>(&h);
            h = __floats2half2_rn(aA01.x * qrA0, aA01.y * qrA0); qaA[2] = *reinterpret_cast<u32*>(&h);
            h = __floats2half2_rn(aA11.x * qrA1, aA11.y * qrA1); qaA[3] = *reinterpret_cast<u32*>(&h);
            h = __floats2half2_rn(aB00.x * qrB0, aB00.y * qrB0); qaB[0] = *reinterpret_cast<u32*>(&h);
            h = __floats2half2_rn(aB10.x * qrB1, aB10.y * qrB1); qaB[1] = *reinterpret_cast<u32*>(&h);
            h = __floats2half2_rn(aB01.x * qrB0, aB01.y * qrB0); qaB[2] = *reinterpret_cast<u32*>(&h);
            h = __floats2half2_rn(aB11.x * qrB1, aB11.y * qrB1); qaB[3] = *reinterpret_cast<u32*>(&h);
        }

        float oA0[4] = {0,0,0,0}, oA1[4] = {0,0,0,0};
        float oB0[4] = {0,0,0,0}, oB1[4] = {0,0,0,0};
        float lA0 = 0.f, lA1 = 0.f, lB0 = 0.f, lB1 = 0.f;

        const uint2* bpA = biasF + ((size_t)(hd * 16 + qbA) * 32) * 32 + lane;
        const uint2* bpB = biasF + ((size_t)(hd * 16 + qbB) * 32) * 32 + lane;

        #pragma unroll 2
        for (int jp = 0; jp < 16; jp++) {
            const int j0a = (2 * jp) * 8;
            const int j0b = (2 * jp + 1) * 8;
            uint2 bA0 = __ldg(&bpA[(2 * jp) * 32]);
            uint2 bA1 = __ldg(&bpA[(2 * jp + 1) * 32]);
            uint2 bB0 = __ldg(&bpB[(2 * jp) * 32]);
            uint2 bB1 = __ldg(&bpB[(2 * jp + 1) * 32]);

            u32 kh0 = *reinterpret_cast<u32*>(&sm[SKH + (j0a+g)*24 + 2*t]);
            u32 kh1 = *reinterpret_cast<u32*>(&sm[SKH + (j0a+g)*24 + 2*t + 8]);
            u32 kl0 = *reinterpret_cast<u32*>(&sm[SKL + (j0a+g)*24 + 2*t]);
            u32 kl1 = *reinterpret_cast<u32*>(&sm[SKL + (j0a+g)*24 + 2*t + 8]);
            u32 mh0 = *reinterpret_cast<u32*>(&sm[SKH + (j0b+g)*24 + 2*t]);
            u32 mh1 = *reinterpret_cast<u32*>(&sm[SKH + (j0b+g)*24 + 2*t + 8]);
            u32 ml0 = *reinterpret_cast<u32*>(&sm[SKL + (j0b+g)*24 + 2*t]);
            u32 ml1 = *reinterpret_cast<u32*>(&sm[SKL + (j0b+g)*24 + 2*t + 8]);

            float sAa0=0,sAa1=0,sAa2=0,sAa3=0, sAb0=0,sAb1=0,sAb2=0,sAb3=0;
            MMA16816(sAa0,sAa1,sAa2,sAa3, qaA[0],qaA[1],qaA[2],qaA[3], kh0,kh1);
            MMA16816(sAa0,sAa1,sAa2,sAa3, qaA[0],qaA[1],qaA[2],qaA[3], kl0,kl1);
            MMA16816(sAb0,sAb1,sAb2,sAb3, qaA[0],qaA[1],qaA[2],qaA[3], mh0,mh1);
            MMA16816(sAb0,sAb1,sAb2,sAb3, qaA[0],qaA[1],qaA[2],qaA[3], ml0,ml1);
            float sBa0=0,sBa1=0,sBa2=0,sBa3=0, sBb0=0,sBb1=0,sBb2=0,sBb3=0;
            MMA16816(sBa0,sBa1,sBa2,sBa3, qaB[0],qaB[1],qaB[2],qaB[3], kh0,kh1);
            MMA16816(sBa0,sBa1,sBa2,sBa3, qaB[0],qaB[1],qaB[2],qaB[3], kl0,kl1);
            MMA16816(sBb0,sBb1,sBb2,sBb3, qaB[0],qaB[1],qaB[2],qaB[3], mh0,mh1);
            MMA16816(sBb0,sBb1,sBb2,sBb3, qaB[0],qaB[1],qaB[2],qaB[3], ml0,ml1);

            float2 f;
            f = __half22float2(*reinterpret_cast<__half2*>(&bA0.x));
            float pA0 = ex2(sAa0 + f.x), pA1 = ex2(sAa1 + f.y);
            f = __half22float2(*reinterpret_cast<__half2*>(&bA0.y));
            float pA2 = ex2(sAa2 + f.x), pA3 = ex2(sAa3 + f.y);
            f = __half22float2(*reinterpret_cast<__half2*>(&bA1.x));
            float pA4 = ex2(sAb0 + f.x), pA5 = ex2(sAb1 + f.y);
            f = __half22float2(*reinterpret_cast<__half2*>(&bA1.y));
            float pA6 = ex2(sAb2 + f.x), pA7 = ex2(sAb3 + f.y);
            lA0 += pA0 + pA1 + pA4 + pA5;
            lA1 += pA2 + pA3 + pA6 + pA7;

            f = __half22float2(*reinterpret_cast<__half2*>(&bB0.x));
            float pB0 = ex2(sBa0 + f.x), pB1 = ex2(sBa1 + f.y);
            f = __half22float2(*reinterpret_cast<__half2*>(&bB0.y));
            float pB2 = ex2(sBa2 + f.x), pB3 = ex2(sBa3 + f.y);
            f = __half22float2(*reinterpret_cast<__half2*>(&bB1.x));
            float pB4 = ex2(sBb0 + f.x), pB5 = ex2(sBb1 + f.y);
            f = __half22float2(*reinterpret_cast<__half2*>(&bB1.y));
            float pB6 = ex2(sBb2 + f.x), pB7 = ex2(sBb3 + f.y);
            lB0 += pB0 + pB1 + pB4 + pB5;
            lB1 += pB2 + pB3 + pB6 + pB7;

            __half2 h;
            u32 aA0c, aA1c, aA2c, aA3c, aB0c, aB1c, aB2c, aB3c;
            h = __floats2half2_rn(pA0, pA1); aA0c = *reinterpret_cast<u32*>(&h);
            h = __floats2half2_rn(pA2, pA3); aA1c = *reinterpret_cast<u32*>(&h);
            h = __floats2half2_rn(pA4, pA5); aA2c = *reinterpret_cast<u32*>(&h);
            h = __floats2half2_rn(pA6, pA7); aA3c = *reinterpret_cast<u32*>(&h);
            h = __floats2half2_rn(pB0, pB1); aB0c = *reinterpret_cast<u32*>(&h);
            h = __floats2half2_rn(pB2, pB3); aB1c = *reinterpret_cast<u32*>(&h);
            h = __floats2half2_rn(pB4, pB5); aB2c = *reinterpret_cast<u32*>(&h);
            h = __floats2half2_rn(pB6, pB7); aB3c = *reinterpret_cast<u32*>(&h);

            const int jb = jp * 16;
            u32 vh0 = *reinterpret_cast<u32*>(&sm[SVTH + g*264 + jb + 2*t]);
            u32 vh1 = *reinterpret_cast<u32*>(&sm[SVTH + g*264 + jb + 2*t + 8]);
            u32 wh0 = *reinterpret_cast<u32*>(&sm[SVTH + (8+g)*264 + jb + 2*t]);
            u32 wh1 = *reinterpret_cast<u32*>(&sm[SVTH + (8+g)*264 + jb + 2*t + 8]);

            MMA16816(oA0[0],oA0[1],oA0[2],oA0[3], aA0c,aA1c,aA2c,aA3c, vh0,vh1);
            MMA16816(oA1[0],oA1[1],oA1[2],oA1[3], aA0c,aA1c,aA2c,aA3c, wh0,wh1);
            MMA16816(oB0[0],oB0[1],oB0[2],oB0[3], aB0c,aB1c,aB2c,aB3c, vh0,vh1);
            MMA16816(oB1[0],oB1[1],oB1[2],oB1[3], aB0c,aB1c,aB2c,aB3c, wh0,wh1);
        }

        lA0 += __shfl_xor_sync(0xffffffffu, lA0, 1);
        lA0 += __shfl_xor_sync(0xffffffffu, lA0, 2);
        lA1 += __shfl_xor_sync(0xffffffffu, lA1, 1);
        lA1 += __shfl_xor_sync(0xffffffffu, lA1, 2);
        lB0 += __shfl_xor_sync(0xffffffffu, lB0, 1);
        lB0 += __shfl_xor_sync(0xffffffffu, lB0, 2);
        lB1 += __shfl_xor_sync(0xffffffffu, lB1, 1);
        lB1 += __shfl_xor_sync(0xffffffffu, lB1, 2);
        const float iA0 = 1.f / lA0, iA1 = 1.f / lA1;
        const float iB0 = 1.f / lB0, iB1 = 1.f / lB1;

        const int col = hd * HD + 2 * t;
        *reinterpret_cast<__half2*>(&attn_out[(size_t)mA0 * C_DIM + col]) =
            __floats2half2_rn(oA0[0] * iA0, oA0[1] * iA0);
        *reinterpret_cast<__half2*>(&attn_out[(size_t)mA1 * C_DIM + col]) =
            __floats2half2_rn(oA0[2] * iA1, oA0[3] * iA1);
        *reinterpret_cast<__half2*>(&attn_out[(size_t)mA0 * C_DIM + col + 8]) =
            __floats2half2_rn(oA1[0] * iA0, oA1[1] * iA0);
        *reinterpret_cast<__half2*>(&attn_out[(size_t)mA1 * C_DIM + col + 8]) =
            __floats2half2_rn(oA1[2] * iA1, oA1[3] * iA1);
        *reinterpret_cast<__half2*>(&attn_out[(size_t)mB0 * C_DIM + col]) =
            __floats2half2_rn(oB0[0] * iB0, oB0[1] * iB0);
        *reinterpret_cast<__half2*>(&attn_out[(size_t)mB1 * C_DIM + col]) =
            __floats2half2_rn(oB0[2] * iB1, oB0[3] * iB1);
        *reinterpret_cast<__half2*>(&attn_out[(size_t)mB0 * C_DIM + col + 8]) =
            __floats2half2_rn(oB1[0] * iB0, oB1[1] * iB0);
        *reinterpret_cast<__half2*>(&attn_out[(size_t)mB1 * C_DIM + col + 8]) =
            __floats2half2_rn(oB1[2] * iB1, oB1[3] * iB1);
    }
}

// ---------------------------------------------------------------------------
extern "C" void kernel_launch(void* const* d_in, const int* in_sizes, int n_in,
                              void* d_out, int out_size)
{
    const float* x           = (const float*)d_in[0];
    const float* qkv_w       = (const float*)d_in[1];
    const float* qkv_b       = (const float*)d_in[2];
    const float* proj_w      = (const float*)d_in[3];
    const float* proj_b      = (const float*)d_in[4];
    const float* logit_scale = (const float*)d_in[5];
    const float* rpb_table   = (const float*)d_in[6];
    const float* n1w         = (const float*)d_in[7];
    const float* n1b         = (const float*)d_in[8];
    const float* n2w         = (const float*)d_in[9];
    const float* n2b         = (const float*)d_in[10];
    const float* fc1_w       = (const float*)d_in[11];
    const float* fc1_b       = (const float*)d_in[12];
    const float* fc2_w       = (const float*)d_in[13];
    const float* fc2_b       = (const float*)d_in[14];
    const int*   rpi         = (const int*)d_in[17];
    float* out = (float*)d_out;

    float *p_x1;
    __half *p_qkvh, *p_attnh, *p_hidh;
    uint2 *p_biasF;
    cudaGetSymbolAddress((void**)&p_qkvh,  g_qkvh);
    cudaGetSymbolAddress((void**)&p_biasF, g_biasF);
    cudaGetSymbolAddress((void**)&p_attnh, g_attnh);
    cudaGetSymbolAddress((void**)&p_x1,    g_x1);
    cudaGetSymbolAddress((void**)&p_hidh,  g_hidh);

    // 1) bias fragments (pre-scaled by log2e)
    biasf_kernel<<<dim3(16 * 32, NH), 32>>>(rpi, rpb_table, p_biasF);

    // 2) QKV: fp32 A, fp16 C
    hgemm_kernel<false,true,0><<<dim3(384/128, M_TOK/128), 256>>>(
        x, qkv_w, qkv_b, p_qkvh, M_TOK, 384, 128, nullptr, nullptr, nullptr);

    // 3) paired tensor-core window attention
    attn_tc_kernel<<<dim3(NWIN, NH), 128>>>(p_qkvh, p_biasF, logit_scale, p_attnh);

    // 4) proj + fused LN + residual
    hgemm_kernel<true,false,2><<<dim3(1, M_TOK/128), 256>>>(
        p_attnh, proj_w, proj_b, p_x1, M_TOK, 128, 128, x, n1w, n1b);

    // 5) fc1 + GELU
    hgemm_kernel<false,true,1><<<dim3(256/128, M_TOK/128), 256>>>(
        p_x1, fc1_w, fc1_b, p_hidh, M_TOK, 256, 128, nullptr, nullptr, nullptr);

    // 6) fc2 + fused LN + residual
    hgemm_kernel<true,false,2><<<dim3(1, M_TOK/128), 256>>>(
        p_hidh, fc2_w, fc2_b, out, M_TOK, 128, 256, p_x1, n2w, n2b);
}

// round 15
// speedup vs baseline: 1.6233x; 1.0348x over previous
#include <cuda_runtime.h>
#include <cuda_fp16.h>
#include <cuda_bf16.h>
#include <math_constants.h>

// ---------------------------------------------------------------------------
// SwinV2 block: window cosine-attention + res-post-norm MLP
// b=2, H=W=192, C=128, WS=16, NH=8, d=16
// R11 GEMMs + paired attention with single-MMA scores (S = qh*kh; the k-lo
// correction dropped — precision budget measured sufficient).
// ---------------------------------------------------------------------------

#define M_TOK   73728
#define C_DIM   128
#define NH      8
#define HD      16
#define NWIN    288
#define NTOK    256
#define IMG     192
#define WPR     12
#define LOG2E   1.4426950408889634f

typedef unsigned int u32;

__device__ __half g_qkvh [ (size_t)M_TOK * 384 ];
__device__ uint2  g_biasF[ (size_t)NH * 16 * 32 * 32 ];
__device__ __half g_attnh[ (size_t)M_TOK * C_DIM ];
__device__ float  g_x1   [ (size_t)M_TOK * C_DIM ];
__device__ __half g_hidh [ (size_t)M_TOK * 256 ];

#define MMA16816(d0,d1,d2,d3,a0,a1,a2,a3,b0,b1)                          \
    asm volatile(                                                        \
        "mma.sync.aligned.m16n8k16.row.col.f32.f16.f16.f32 "             \
        "{%0,%1,%2,%3}, {%4,%5,%6,%7}, {%8,%9}, {%0,%1,%2,%3};"          \
        : "+f"(d0), "+f"(d1), "+f"(d2), "+f"(d3)                         \
        : "r"(a0), "r"(a1), "r"(a2), "r"(a3), "r"(b0), "r"(b1))

__device__ __forceinline__ float ex2(float x)
{
    float r;
    asm("ex2.approx.f32 %0, %1;" : "=f"(r) : "f"(x));
    return r;
}

// ---------------------------------------------------------------------------
// fp16 tensor-core GEMM (R11 structure, unchanged).
// ---------------------------------------------------------------------------
template<bool A_HALF, bool C_HALF, int ACT>
__global__ __launch_bounds__(256) void hgemm_kernel(
    const void* __restrict__ Av, const float* __restrict__ B,
    const float* __restrict__ bias, void* __restrict__ Cv,
    int M, int N, int K,
    const float* __restrict__ res,
    const float* __restrict__ lnw, const float* __restrict__ lnb)
{
    __shared__ __half As[128][40];
    __shared__ __half Bs[32][136];
    __shared__ float2 red[128][4];

    const float*  Af = (const float*)Av;
    const __half* Ah = (const __half*)Av;
    float*  Cf = (float*)Cv;
    __half* Ch = (__half*)Cv;

    const int tid  = threadIdx.x;
    const int lane = tid & 31;
    const int wid  = tid >> 5;
    const int warp_m = wid >> 2;
    const int warp_n = wid & 3;
    const int brow = blockIdx.y * 128;
    const int bcol = blockIdx.x * 128;

    const int a_m0 = tid >> 3;
    const int a_k4 = (tid & 7) << 2;
    const int a_m0h = tid >> 2;
    const int a_k8  = (tid & 3) << 3;
    const int b_k0 = tid >> 5;
    const int b_n4 = (tid & 31) << 2;

    const u32 a_smem = (u32)__cvta_generic_to_shared(&As[0][0]);
    const u32 b_smem = (u32)__cvta_generic_to_shared(&Bs[0][0]);

    float acc[4][4][4];
    #pragma unroll
    for (int mi = 0; mi < 4; mi++)
        #pragma unroll
        for (int ni = 0; ni < 4; ni++)
            #pragma unroll
            for (int z = 0; z < 4; z++) acc[mi][ni][z] = 0.f;

    float4 a_pf[4];
    uint4  a_pfh[2];
    float4 b_pf[4];
    if (A_HALF) {
        #pragma unroll
        for (int t = 0; t < 2; t++)
            a_pfh[t] = *reinterpret_cast<const uint4*>(
                &Ah[(size_t)(brow + a_m0h + t * 64) * K + a_k8]);
    } else {
        #pragma unroll
        for (int t = 0; t < 4; t++)
            a_pf[t] = *reinterpret_cast<const float4*>(
                &Af[(size_t)(brow + a_m0 + t * 32) * K + a_k4]);
    }
    #pragma unroll
    for (int t = 0; t < 4; t++)
        b_pf[t] = *reinterpret_cast<const float4*>(
            &B[(size_t)(b_k0 + t * 8) * N + bcol + b_n4]);

    for (int kt = 0; kt < K; kt += 32) {
        if (A_HALF) {
            #pragma unroll
            for (int t = 0; t < 2; t++)
                *reinterpret_cast<uint4*>(&As[a_m0h + t * 64][a_k8]) = a_pfh[t];
        } else {
            #pragma unroll
            for (int t = 0; t < 4; t++) {
                __half2 h0 = __float22half2_rn(make_float2(a_pf[t].x, a_pf[t].y));
                __half2 h1 = __float22half2_rn(make_float2(a_pf[t].z, a_pf[t].w));
                *reinterpret_cast<__half2*>(&As[a_m0 + t * 32][a_k4 + 0]) = h0;
                *reinterpret_cast<__half2*>(&As[a_m0 + t * 32][a_k4 + 2]) = h1;
            }
        }
        #pragma unroll
        for (int t = 0; t < 4; t++) {
            __half2 g0 = __float22half2_rn(make_float2(b_pf[t].x, b_pf[t].y));
            __half2 g1 = __float22half2_rn(make_float2(b_pf[t].z, b_pf[t].w));
            *reinterpret_cast<__half2*>(&Bs[b_k0 + t * 8][b_n4 + 0]) = g0;
            *reinterpret_cast<__half2*>(&Bs[b_k0 + t * 8][b_n4 + 2]) = g1;
        }
        __syncthreads();

        if (kt + 32 < K) {
            if (A_HALF) {
                #pragma unroll
                for (int t = 0; t < 2; t++)
                    a_pfh[t] = *reinterpret_cast<const uint4*>(
                        &Ah[(size_t)(brow + a_m0h + t * 64) * K + kt + 32 + a_k8]);
            } else {
                #pragma unroll
                for (int t = 0; t < 4; t++)
                    a_pf[t] = *reinterpret_cast<const float4*>(
                        &Af[(size_t)(brow + a_m0 + t * 32) * K + kt + 32 + a_k4]);
            }
            #pragma unroll
            for (int t = 0; t < 4; t++)
                b_pf[t] = *reinterpret_cast<const float4*>(
                    &B[(size_t)(kt + 32 + b_k0 + t * 8) * N + bcol + b_n4]);
        }

        #pragma unroll
        for (int ks = 0; ks < 32; ks += 16) {
            u32 af[4][4];
            #pragma unroll
            for (int mi = 0; mi < 4; mi++) {
                int r = warp_m * 64 + mi * 16 + (lane & 15);
                int c = ks + ((lane >> 4) << 3);
                u32 addr = a_smem + (u32)(r * 40 + c) * 2u;
                asm volatile(
                    "ldmatrix.sync.aligned.m8n8.x4.shared.b16 {%0,%1,%2,%3}, [%4];"
                    : "=r"(af[mi][0]), "=r"(af[mi][1]), "=r"(af[mi][2]), "=r"(af[mi][3])
                    : "r"(addr));
            }
            u32 bf[4][2];
            #pragma unroll
            for (int p = 0; p < 2; p++) {
                int r = ks + (lane & 15);
                int c = warp_n * 32 + p * 16 + ((lane >> 4) << 3);
                u32 addr = b_smem + (u32)(r * 136 + c) * 2u;
                asm volatile(
                    "ldmatrix.sync.aligned.m8n8.x4.trans.shared.b16 {%0,%1,%2,%3}, [%4];"
                    : "=r"(bf[2*p][0]), "=r"(bf[2*p][1]),
                      "=r"(bf[2*p+1][0]), "=r"(bf[2*p+1][1])
                    : "r"(addr));
            }
            #pragma unroll
            for (int mi = 0; mi < 4; mi++)
                #pragma unroll
                for (int ni = 0; ni < 4; ni++) {
                    MMA16816(acc[mi][ni][0], acc[mi][ni][1],
                             acc[mi][ni][2], acc[mi][ni][3],
                             af[mi][0], af[mi][1], af[mi][2], af[mi][3],
                             bf[ni][0], bf[ni][1]);
                }
        }
        __syncthreads();
    }

    const int g = lane >> 2;
    const int t = lane & 3;

    if (ACT == 2) {
        #pragma unroll
        for (int mi = 0; mi < 4; mi++) {
            #pragma unroll
            for (int ni = 0; ni < 4; ni++) {
                const int c = warp_n * 32 + ni * 8 + (t << 1);
                float2 bb = *reinterpret_cast<const float2*>(&bias[c]);
                acc[mi][ni][0] += bb.x; acc[mi][ni][1] += bb.y;
                acc[mi][ni][2] += bb.x; acc[mi][ni][3] += bb.y;
            }
            float s0 = 0.f, q0 = 0.f, s1 = 0.f, q1 = 0.f;
            #pragma unroll
            for (int ni = 0; ni < 4; ni++) {
                s0 += acc[mi][ni][0] + acc[mi][ni][1];
                q0 += acc[mi][ni][0]*acc[mi][ni][0] + acc[mi][ni][1]*acc[mi][ni][1];
                s1 += acc[mi][ni][2] + acc[mi][ni][3];
                q1 += acc[mi][ni][2]*acc[mi][ni][2] + acc[mi][ni][3]*acc[mi][ni][3];
            }
            s0 += __shfl_xor_sync(0xffffffffu, s0, 1);
            s0 += __shfl_xor_sync(0xffffffffu, s0, 2);
            q0 += __shfl_xor_sync(0xffffffffu, q0, 1);
            q0 += __shfl_xor_sync(0xffffffffu, q0, 2);
            s1 += __shfl_xor_sync(0xffffffffu, s1, 1);
            s1 += __shfl_xor_sync(0xffffffffu, s1, 2);
            q1 += __shfl_xor_sync(0xffffffffu, q1, 1);
            q1 += __shfl_xor_sync(0xffffffffu, q1, 2);
            if (t == 0) {
                const int rl = warp_m * 64 + mi * 16 + g;
                red[rl][warp_n]     = make_float2(s0, q0);
                red[rl + 8][warp_n] = make_float2(s1, q1);
            }
        }
        __syncthreads();

        #pragma unroll
        for (int mi = 0; mi < 4; mi++) {
            const int rl0 = warp_m * 64 + mi * 16 + g;
            const int rl1 = rl0 + 8;
            float2 p;
            float s0 = 0.f, q0 = 0.f, s1 = 0.f, q1 = 0.f;
            #pragma unroll
            for (int w = 0; w < 4; w++) {
                p = red[rl0][w]; s0 += p.x; q0 += p.y;
                p = red[rl1][w]; s1 += p.x; q1 += p.y;
            }
            const float mu0 = s0 * (1.f/128.f);
            const float mu1 = s1 * (1.f/128.f);
            const float rs0 = rsqrtf(q0 * (1.f/128.f) - mu0*mu0 + 1e-5f);
            const float rs1 = rsqrtf(q1 * (1.f/128.f) - mu1*mu1 + 1e-5f);

            const size_t gr0 = (size_t)(brow + rl0) * 128;
            const size_t gr1 = (size_t)(brow + rl1) * 128;
            #pragma unroll
            for (int ni = 0; ni < 4; ni++) {
                const int c = warp_n * 32 + ni * 8 + (t << 1);
                float2 wv = *reinterpret_cast<const float2*>(&lnw[c]);
                float2 bv = *reinterpret_cast<const float2*>(&lnb[c]);
                float2 r0v = *reinterpret_cast<const float2*>(&res[gr0 + c]);
                float2 r1v = *reinterpret_cast<const float2*>(&res[gr1 + c]);
                float2 o0, o1;
                o0.x = r0v.x + (acc[mi][ni][0] - mu0) * rs0 * wv.x + bv.x;
                o0.y = r0v.y + (acc[mi][ni][1] - mu0) * rs0 * wv.y + bv.y;
                o1.x = r1v.x + (acc[mi][ni][2] - mu1) * rs1 * wv.x + bv.x;
                o1.y = r1v.y + (acc[mi][ni][3] - mu1) * rs1 * wv.y + bv.y;
                *reinterpret_cast<float2*>(&Cf[gr0 + c]) = o0;
                *reinterpret_cast<float2*>(&Cf[gr1 + c]) = o1;
            }
        }
        return;
    }

    #pragma unroll
    for (int mi = 0; mi < 4; mi++) {
        #pragma unroll
        for (int ni = 0; ni < 4; ni++) {
            const int r0 = brow + warp_m * 64 + mi * 16 + g;
            const int c  = bcol + warp_n * 32 + ni * 8 + (t << 1);
            float2 bb = *reinterpret_cast<const float2*>(&bias[c]);
            float2 v0, v1;
            v0.x = acc[mi][ni][0] + bb.x; v0.y = acc[mi][ni][1] + bb.y;
            v1.x = acc[mi][ni][2] + bb.x; v1.y = acc[mi][ni][3] + bb.y;
            if (ACT == 1) {
                v0.x *= normcdff(v0.x); v0.y *= normcdff(v0.y);
                v1.x *= normcdff(v1.x); v1.y *= normcdff(v1.y);
            }
            if (C_HALF) {
                *reinterpret_cast<__half2*>(&Ch[(size_t)r0 * N + c]) =
                    __float22half2_rn(v0);
                *reinterpret_cast<__half2*>(&Ch[(size_t)(r0 + 8) * N + c]) =
                    __float22half2_rn(v1);
            } else {
                *reinterpret_cast<float2*>(&Cf[(size_t)r0 * N + c])       = v0;
                *reinterpret_cast<float2*>(&Cf[(size_t)(r0 + 8) * N + c]) = v1;
            }
        }
    }
}

// ---------------------------------------------------------------------------
// Bias in mma C-fragment layout, pre-multiplied by log2(e). 256-thread blocks.
// ---------------------------------------------------------------------------
__global__ void biasf_kernel(const int* __restrict__ rpi,
                             const float* __restrict__ table,
                             uint2* __restrict__ biasF)
{
    const int unit = blockIdx.x * 8 + (threadIdx.x >> 5);  // (qb,jt) pair id
    const int qb = unit >> 5;
    const int jt = unit & 31;
    const int hd = blockIdx.y;
    const int lane = threadIdx.x & 31;
    const int g = lane >> 2, t = lane & 3;
    const int i0 = qb * 16, j0 = jt * 8;

    float b00 = table[rpi[(i0 + g)     * NTOK + j0 + 2*t    ] * NH + hd] * LOG2E;
    float b01 = table[rpi[(i0 + g)     * NTOK + j0 + 2*t + 1] * NH + hd] * LOG2E;
    float b10 = table[rpi[(i0 + g + 8) * NTOK + j0 + 2*t    ] * NH + hd] * LOG2E;
    float b11 = table[rpi[(i0 + g + 8) * NTOK + j0 + 2*t + 1] * NH + hd] * LOG2E;

    uint2 r;
    *reinterpret_cast<__half2*>(&r.x) = __floats2half2_rn(b00, b01);
    *reinterpret_cast<__half2*>(&r.y) = __floats2half2_rn(b10, b11);
    biasF[((size_t)(hd * 16 + qb) * 32 + jt) * 32 + lane] = r;
}

// ---------------------------------------------------------------------------
// Paired tensor-core window attention, single-MMA scores (no k-lo split).
// smem: Kh [256][24] + Vt [16][264] = 20.4 KB.
// ---------------------------------------------------------------------------
#define SKH  0
#define SVTH (256*24)
#define ATTN_SMEM_HALFS (256*24 + 16*264)

__global__ __launch_bounds__(128, 4) void attn_tc_kernel(
    const __half* __restrict__ qkv, const uint2* __restrict__ biasF,
    const float* __restrict__ logit_scale, __half* __restrict__ attn_out)
{
    __shared__ __half sm[ATTN_SMEM_HALFS];

    const int wi = blockIdx.x;
    const int hd = blockIdx.y;
    const int tid = threadIdx.x;

    const int bimg = wi / 144;
    const int wrem = wi % 144;
    const int wr = wrem / WPR, wc = wrem % WPR;
    const int rowbase = bimg * (IMG * IMG) + (wr * 16) * IMG + wc * 16;

    const float scale = __expf(fminf(logit_scale[hd], 4.6051702f));
    const float qmul  = scale * LOG2E;

    for (int tok = tid; tok < NTOK; tok += 128) {
        const int m = rowbase + (tok >> 4) * IMG + (tok & 15);
        const __half* base = qkv + (size_t)m * 384 + hd * HD;

        uint4 kraw0 = *reinterpret_cast<const uint4*>(base + 128);
        uint4 kraw1 = *reinterpret_cast<const uint4*>(base + 136);
        uint4 vraw0 = *reinterpret_cast<const uint4*>(base + 256);
        uint4 vraw1 = *reinterpret_cast<const uint4*>(base + 264);

        float kf[16];
        {
            const __half2* k2a = reinterpret_cast<const __half2*>(&kraw0);
            const __half2* k2b = reinterpret_cast<const __half2*>(&kraw1);
            #pragma unroll
            for (int z = 0; z < 4; z++) {
                float2 f = __half22float2(k2a[z]);
                kf[2*z] = f.x; kf[2*z+1] = f.y;
                f = __half22float2(k2b[z]);
                kf[8+2*z] = f.x; kf[8+2*z+1] = f.y;
            }
        }
        float ks = 0.f;
        #pragma unroll
        for (int z = 0; z < 16; z++) ks += kf[z] * kf[z];
        const float kr = 1.f / fmaxf(sqrtf(ks), 1e-12f);
        #pragma unroll
        for (int z = 0; z < 16; z++)
            sm[SKH + tok*24 + z] = __float2half_rn(kf[z] * kr);

        const __half* vh = reinterpret_cast<const __half*>(&vraw0);
        #pragma unroll
        for (int z = 0; z < 8; z++) sm[SVTH + z*264 + tok] = vh[z];
        vh = reinterpret_cast<const __half*>(&vraw1);
        #pragma unroll
        for (int z = 0; z < 8; z++) sm[SVTH + (8+z)*264 + tok] = vh[z];
    }
    __syncthreads();

    const int warp = tid >> 5;
    const int lane = tid & 31;
    const int g = lane >> 2;
    const int t = lane & 3;

    for (int qp = 0; qp < 2; qp++) {
        const int qbA = warp * 4 + qp * 2;
        const int qbB = qbA + 1;

        int mA0, mA1, mB0, mB1;
        u32 qaA[4], qaB[4];
        {
            const int iA = qbA * 16, iB = qbB * 16;
            const int rA0 = iA + g, rA1 = iA + g + 8;
            const int rB0 = iB + g, rB1 = iB + g + 8;
            mA0 = rowbase + (rA0 >> 4) * IMG + (rA0 & 15);
            mA1 = rowbase + (rA1 >> 4) * IMG + (rA1 & 15);
            mB0 = rowbase + (rB0 >> 4) * IMG + (rB0 & 15);
            mB1 = rowbase + (rB1 >> 4) * IMG + (rB1 & 15);

            const __half* pA0 = qkv + (size_t)mA0 * 384 + hd * HD;
            const __half* pA1 = qkv + (size_t)mA1 * 384 + hd * HD;
            const __half* pB0 = qkv + (size_t)mB0 * 384 + hd * HD;
            const __half* pB1 = qkv + (size_t)mB1 * 384 + hd * HD;

            float2 aA00 = __half22float2(*reinterpret_cast<const __half2*>(pA0 + 2*t));
            float2 aA01 = __half22float2(*reinterpret_cast<const __half2*>(pA0 + 2*t + 8));
            float2 aA10 = __half22float2(*reinterpret_cast<const __half2*>(pA1 + 2*t));
            float2 aA11 = __half22float2(*reinterpret_cast<const __half2*>(pA1 + 2*t + 8));
            float2 aB00 = __half22float2(*reinterpret_cast<const __half2*>(pB0 + 2*t));
            float2 aB01 = __half22float2(*reinterpret_cast<const __half2*>(pB0 + 2*t + 8));
            float2 aB10 = __half22float2(*reinterpret_cast<const __half2*>(pB1 + 2*t));
            float2 aB11 = __half22float2(*reinterpret_cast<const __half2*>(pB1 + 2*t + 8));

            float sA0 = aA00.x*aA00.x + aA00.y*aA00.y + aA01.x*aA01.x + aA01.y*aA01.y;
            float sA1 = aA10.x*aA10.x + aA10.y*aA10.y + aA11.x*aA11.x + aA11.y*aA11.y;
            float sB0 = aB00.x*aB00.x + aB00.y*aB00.y + aB01.x*aB01.x + aB01.y*aB01.y;
            float sB1 = aB10.x*aB10.x + aB10.y*aB10.y + aB11.x*aB11.x + aB11.y*aB11.y;
            sA0 += __shfl_xor_sync(0xffffffffu, sA0, 1);
            sA0 += __shfl_xor_sync(0xffffffffu, sA0, 2);
            sA1 += __shfl_xor_sync(0xffffffffu, sA1, 1);
            sA1 += __shfl_xor_sync(0xffffffffu, sA1, 2);
            sB0 += __shfl_xor_sync(0xffffffffu, sB0, 1);
            sB0 += __shfl_xor_sync(0xffffffffu, sB0, 2);
            sB1 += __shfl_xor_sync(0xffffffffu, sB1, 1);
            sB1 += __shfl_xor_sync(0xffffffffu, sB1, 2);
            const float qrA0 = qmul / fmaxf(sqrtf(sA0), 1e-12f);
            const float qrA1 = qmul / fmaxf(sqrtf(sA1), 1e-12f);
            const float qrB0 = qmul / fmaxf(sqrtf(sB0), 1e-12f);
            const float qrB1 = qmul / fmaxf(sqrtf(sB1), 1e-12f);

            __half2 h;
            h = __floats2half2_rn(aA00.x * qrA0, aA00.y * qrA0); qaA[0] = *reinterpret_cast<u32*>(&h);
            h = __floats2half2_rn(aA10.x * qrA1, aA10.y * qrA1); qaA[1] = *reinterpret_cast<u32*>(&h);
            h = __floats2half2_rn(aA01.x * qrA0, aA01.y * qrA0); qaA[2] = *reinterpret_cast<u32*>(&h);
            h = __floats2half2_rn(aA11.x * qrA1, aA11.y * qrA1); qaA[3] = *reinterpret_cast<u32*>(&h);
            h = __floats2half2_rn(aB00.x * qrB0, aB00.y * qrB0); qaB[0] = *reinterpret_cast<u32*>(&h);
            h = __floats2half2_rn(aB10.x * qrB1, aB10.y * qrB1); qaB[1] = *reinterpret_cast<u32*>(&h);
            h = __floats2half2_rn(aB01.x * qrB0, aB01.y * qrB0); qaB[2] = *reinterpret_cast<u32*>(&h);
            h = __floats2half2_rn(aB11.x * qrB1, aB11.y * qrB1); qaB[3] = *reinterpret_cast<u32*>(&h);
        }

        float oA0[4] = {0,0,0,0}, oA1[4] = {0,0,0,0};
        float oB0[4] = {0,0,0,0}, oB1[4] = {0,0,0,0};
        float lA0 = 0.f, lA1 = 0.f, lB0 = 0.f, lB1 = 0.f;

        const uint2* bpA = biasF + ((size_t)(hd * 16 + qbA) * 32) * 32 + lane;
        const uint2* bpB = biasF + ((size_t)(hd * 16 + qbB) * 32) * 32 + lane;

        #pragma unroll 2
        for (int jp = 0; jp < 16; jp++) {
            const int j0a = (2 * jp) * 8;
            const int j0b = (2 * jp + 1) * 8;
            uint2 bA0 = __ldg(&bpA[(2 * jp) * 32]);
            uint2 bA1 = __ldg(&bpA[(2 * jp + 1) * 32]);
            uint2 bB0 = __ldg(&bpB[(2 * jp) * 32]);
            uint2 bB1 = __ldg(&bpB[(2 * jp + 1) * 32]);

            u32 kh0 = *reinterpret_cast<u32*>(&sm[SKH + (j0a+g)*24 + 2*t]);
            u32 kh1 = *reinterpret_cast<u32*>(&sm[SKH + (j0a+g)*24 + 2*t + 8]);
            u32 mh0 = *reinterpret_cast<u32*>(&sm[SKH + (j0b+g)*24 + 2*t]);
            u32 mh1 = *reinterpret_cast<u32*>(&sm[SKH + (j0b+g)*24 + 2*t + 8]);

            float sAa0=0,sAa1=0,sAa2=0,sAa3=0, sAb0=0,sAb1=0,sAb2=0,sAb3=0;
            MMA16816(sAa0,sAa1,sAa2,sAa3, qaA[0],qaA[1],qaA[2],qaA[3], kh0,kh1);
            MMA16816(sAb0,sAb1,sAb2,sAb3, qaA[0],qaA[1],qaA[2],qaA[3], mh0,mh1);
            float sBa0=0,sBa1=0,sBa2=0,sBa3=0, sBb0=0,sBb1=0,sBb2=0,sBb3=0;
            MMA16816(sBa0,sBa1,sBa2,sBa3, qaB[0],qaB[1],qaB[2],qaB[3], kh0,kh1);
            MMA16816(sBb0,sBb1,sBb2,sBb3, qaB[0],qaB[1],qaB[2],qaB[3], mh0,mh1);

            float2 f;
            f = __half22float2(*reinterpret_cast<__half2*>(&bA0.x));
            float pA0 = ex2(sAa0 + f.x), pA1 = ex2(sAa1 + f.y);
            f = __half22float2(*reinterpret_cast<__half2*>(&bA0.y));
            float pA2 = ex2(sAa2 + f.x), pA3 = ex2(sAa3 + f.y);
            f = __half22float2(*reinterpret_cast<__half2*>(&bA1.x));
            float pA4 = ex2(sAb0 + f.x), pA5 = ex2(sAb1 + f.y);
            f = __half22float2(*reinterpret_cast<__half2*>(&bA1.y));
            float pA6 = ex2(sAb2 + f.x), pA7 = ex2(sAb3 + f.y);
            lA0 += pA0 + pA1 + pA4 + pA5;
            lA1 += pA2 + pA3 + pA6 + pA7;

            f = __half22float2(*reinterpret_cast<__half2*>(&bB0.x));
            float pB0 = ex2(sBa0 + f.x), pB1 = ex2(sBa1 + f.y);
            f = __half22float2(*reinterpret_cast<__half2*>(&bB0.y));
            float pB2 = ex2(sBa2 + f.x), pB3 = ex2(sBa3 + f.y);
            f = __half22float2(*reinterpret_cast<__half2*>(&bB1.x));
            float pB4 = ex2(sBb0 + f.x), pB5 = ex2(sBb1 + f.y);
            f = __half22float2(*reinterpret_cast<__half2*>(&bB1.y));
            float pB6 = ex2(sBb2 + f.x), pB7 = ex2(sBb3 + f.y);
            lB0 += pB0 + pB1 + pB4 + pB5;
            lB1 += pB2 + pB3 + pB6 + pB7;

            __half2 h;
            u32 aA0c, aA1c, aA2c, aA3c, aB0c, aB1c, aB2c, aB3c;
            h = __floats2half2_rn(pA0, pA1); aA0c = *reinterpret_cast<u32*>(&h);
            h = __floats2half2_rn(pA2, pA3); aA1c = *reinterpret_cast<u32*>(&h);
            h = __floats2half2_rn(pA4, pA5); aA2c = *reinterpret_cast<u32*>(&h);
            h = __floats2half2_rn(pA6, pA7); aA3c = *reinterpret_cast<u32*>(&h);
            h = __floats2half2_rn(pB0, pB1); aB0c = *reinterpret_cast<u32*>(&h);
            h = __floats2half2_rn(pB2, pB3); aB1c = *reinterpret_cast<u32*>(&h);
            h = __floats2half2_rn(pB4, pB5); aB2c = *reinterpret_cast<u32*>(&h);
            h = __floats2half2_rn(pB6, pB7); aB3c = *reinterpret_cast<u32*>(&h);

            const int jb = jp * 16;
            u32 vh0 = *reinterpret_cast<u32*>(&sm[SVTH + g*264 + jb + 2*t]);
            u32 vh1 = *reinterpret_cast<u32*>(&sm[SVTH + g*264 + jb + 2*t + 8]);
            u32 wh0 = *reinterpret_cast<u32*>(&sm[SVTH + (8+g)*264 + jb + 2*t]);
            u32 wh1 = *reinterpret_cast<u32*>(&sm[SVTH + (8+g)*264 + jb + 2*t + 8]);

            MMA16816(oA0[0],oA0[1],oA0[2],oA0[3], aA0c,aA1c,aA2c,aA3c, vh0,vh1);
            MMA16816(oA1[0],oA1[1],oA1[2],oA1[3], aA0c,aA1c,aA2c,aA3c, wh0,wh1);
            MMA16816(oB0[0],oB0[1],oB0[2],oB0[3], aB0c,aB1c,aB2c,aB3c, vh0,vh1);
            MMA16816(oB1[0],oB1[1],oB1[2],oB1[3], aB0c,aB1c,aB2c,aB3c, wh0,wh1);
        }

        lA0 += __shfl_xor_sync(0xffffffffu, lA0, 1);
        lA0 += __shfl_xor_sync(0xffffffffu, lA0, 2);
        lA1 += __shfl_xor_sync(0xffffffffu, lA1, 1);
        lA1 += __shfl_xor_sync(0xffffffffu, lA1, 2);
        lB0 += __shfl_xor_sync(0xffffffffu, lB0, 1);
        lB0 += __shfl_xor_sync(0xffffffffu, lB0, 2);
        lB1 += __shfl_xor_sync(0xffffffffu, lB1, 1);
        lB1 += __shfl_xor_sync(0xffffffffu, lB1, 2);
        const float iA0 = 1.f / lA0, iA1 = 1.f / lA1;
        const float iB0 = 1.f / lB0, iB1 = 1.f / lB1;

        const int col = hd * HD + 2 * t;
        *reinterpret_cast<__half2*>(&attn_out[(size_t)mA0 * C_DIM + col]) =
            __floats2half2_rn(oA0[0] * iA0, oA0[1] * iA0);
        *reinterpret_cast<__half2*>(&attn_out[(size_t)mA1 * C_DIM + col]) =
            __floats2half2_rn(oA0[2] * iA1, oA0[3] * iA1);
        *reinterpret_cast<__half2*>(&attn_out[(size_t)mA0 * C_DIM + col + 8]) =
            __floats2half2_rn(oA1[0] * iA0, oA1[1] * iA0);
        *reinterpret_cast<__half2*>(&attn_out[(size_t)mA1 * C_DIM + col + 8]) =
            __floats2half2_rn(oA1[2] * iA1, oA1[3] * iA1);
        *reinterpret_cast<__half2*>(&attn_out[(size_t)mB0 * C_DIM + col]) =
            __floats2half2_rn(oB0[0] * iB0, oB0[1] * iB0);
        *reinterpret_cast<__half2*>(&attn_out[(size_t)mB1 * C_DIM + col]) =
            __floats2half2_rn(oB0[2] * iB1, oB0[3] * iB1);
        *reinterpret_cast<__half2*>(&attn_out[(size_t)mB0 * C_DIM + col + 8]) =
            __floats2half2_rn(oB1[0] * iB0, oB1[1] * iB0);
        *reinterpret_cast<__half2*>(&attn_out[(size_t)mB1 * C_DIM + col + 8]) =
            __floats2half2_rn(oB1[2] * iB1, oB1[3] * iB1);
    }
}

// ---------------------------------------------------------------------------
extern "C" void kernel_launch(void* const* d_in, const int* in_sizes, int n_in,
                              void* d_out, int out_size)
{
    const float* x           = (const float*)d_in[0];
    const float* qkv_w       = (const float*)d_in[1];
    const float* qkv_b       = (const float*)d_in[2];
    const float* proj_w      = (const float*)d_in[3];
    const float* proj_b      = (const float*)d_in[4];
    const float* logit_scale = (const float*)d_in[5];
    const float* rpb_table   = (const float*)d_in[6];
    const float* n1w         = (const float*)d_in[7];
    const float* n1b         = (const float*)d_in[8];
    const float* n2w         = (const float*)d_in[9];
    const float* n2b         = (const float*)d_in[10];
    const float* fc1_w       = (const float*)d_in[11];
    const float* fc1_b       = (const float*)d_in[12];
    const float* fc2_w       = (const float*)d_in[13];
    const float* fc2_b       = (const float*)d_in[14];
    const int*   rpi         = (const int*)d_in[17];
    float* out = (float*)d_out;

    float *p_x1;
    __half *p_qkvh, *p_attnh, *p_hidh;
    uint2 *p_biasF;
    cudaGetSymbolAddress((void**)&p_qkvh,  g_qkvh);
    cudaGetSymbolAddress((void**)&p_biasF, g_biasF);
    cudaGetSymbolAddress((void**)&p_attnh, g_attnh);
    cudaGetSymbolAddress((void**)&p_x1,    g_x1);
    cudaGetSymbolAddress((void**)&p_hidh,  g_hidh);

    // 1) bias fragments (pre-scaled by log2e), 256-thread blocks
    biasf_kernel<<<dim3(64, NH), 256>>>(rpi, rpb_table, p_biasF);

    // 2) QKV: fp32 A, fp16 C
    hgemm_kernel<false,true,0><<<dim3(384/128, M_TOK/128), 256>>>(
        x, qkv_w, qkv_b, p_qkvh, M_TOK, 384, 128, nullptr, nullptr, nullptr);

    // 3) paired tensor-core window attention (single-MMA scores)
    attn_tc_kernel<<<dim3(NWIN, NH), 128>>>(p_qkvh, p_biasF, logit_scale, p_attnh);

    // 4) proj + fused LN + residual
    hgemm_kernel<true,false,2><<<dim3(1, M_TOK/128), 256>>>(
        p_attnh, proj_w, proj_b, p_x1, M_TOK, 128, 128, x, n1w, n1b);

    // 5) fc1 + GELU
    hgemm_kernel<false,true,1><<<dim3(256/128, M_TOK/128), 256>>>(
        p_x1, fc1_w, fc1_b, p_hidh, M_TOK, 256, 128, nullptr, nullptr, nullptr);

    // 6) fc2 + fused LN + residual
    hgemm_kernel<true,false,2><<<dim3(1, M_TOK/128), 256>>>(
        p_hidh, fc2_w, fc2_b, out, M_TOK, 128, 256, p_x1, n2w, n2b);
}

// round 16
// speedup vs baseline: 1.6399x; 1.0102x over previous
#include <cuda_runtime.h>
#include <cuda_fp16.h>
#include <cuda_bf16.h>
#include <math_constants.h>

// ---------------------------------------------------------------------------
// SwinV2 block: window cosine-attention + res-post-norm MLP
// b=2, H=W=192, C=128, WS=16, NH=8, d=16
// GEMMs: BK=32 + smem ping-pong (1 sync/chunk).
// Attention: shifted fp16x2 exp2 softmax; row-sum via ones-MMA.
// ---------------------------------------------------------------------------

#define M_TOK   73728
#define C_DIM   128
#define NH      8
#define HD      16
#define NWIN    288
#define NTOK    256
#define IMG     192
#define WPR     12
#define LOG2E   1.4426950408889634f

typedef unsigned int u32;

__device__ __half g_qkvh [ (size_t)M_TOK * 384 ];
__device__ float4 g_biasF[ (size_t)NH * 16 * 32 * 32 ];   // fp32 shifted bias, 2MB
__device__ __half g_attnh[ (size_t)M_TOK * C_DIM ];
__device__ float  g_x1   [ (size_t)M_TOK * C_DIM ];
__device__ __half g_hidh [ (size_t)M_TOK * 256 ];

#define MMA16816(d0,d1,d2,d3,a0,a1,a2,a3,b0,b1)                          \
    asm volatile(                                                        \
        "mma.sync.aligned.m16n8k16.row.col.f32.f16.f16.f32 "             \
        "{%0,%1,%2,%3}, {%4,%5,%6,%7}, {%8,%9}, {%0,%1,%2,%3};"          \
        : "+f"(d0), "+f"(d1), "+f"(d2), "+f"(d3)                         \
        : "r"(a0), "r"(a1), "r"(a2), "r"(a3), "r"(b0), "r"(b1))

__device__ __forceinline__ u32 h2ex2(__half2 x)
{
    u32 xi = *reinterpret_cast<u32*>(&x);
    u32 r;
    asm("ex2.approx.f16x2 %0, %1;" : "=r"(r) : "r"(xi));
    return r;
}

// ---------------------------------------------------------------------------
// fp16 tensor-core GEMM, BK=32, smem PING-PONG (single sync per chunk).
// act: 0 none, 1 exact GELU, 2 fused res + LayerNorm (N==128, C fp32).
// ---------------------------------------------------------------------------
template<bool A_HALF, bool C_HALF, int ACT>
__global__ __launch_bounds__(256) void hgemm_kernel(
    const void* __restrict__ Av, const float* __restrict__ B,
    const float* __restrict__ bias, void* __restrict__ Cv,
    int M, int N, int K,
    const float* __restrict__ res,
    const float* __restrict__ lnw, const float* __restrict__ lnb)
{
    __shared__ __half As[2][128][40];
    __shared__ __half Bs[2][32][136];
    __shared__ float2 red[128][4];

    const float*  Af = (const float*)Av;
    const __half* Ah = (const __half*)Av;
    float*  Cf = (float*)Cv;
    __half* Ch = (__half*)Cv;

    const int tid  = threadIdx.x;
    const int lane = tid & 31;
    const int wid  = tid >> 5;
    const int warp_m = wid >> 2;
    const int warp_n = wid & 3;
    const int brow = blockIdx.y * 128;
    const int bcol = blockIdx.x * 128;

    const int a_m0 = tid >> 3;
    const int a_k4 = (tid & 7) << 2;
    const int a_m0h = tid >> 2;
    const int a_k8  = (tid & 3) << 3;
    const int b_k0 = tid >> 5;
    const int b_n4 = (tid & 31) << 2;

    const u32 a_smem0 = (u32)__cvta_generic_to_shared(&As[0][0][0]);
    const u32 b_smem0 = (u32)__cvta_generic_to_shared(&Bs[0][0][0]);
    const u32 A_BUF = 128 * 40 * 2;
    const u32 B_BUF = 32 * 136 * 2;

    float acc[4][4][4];
    #pragma unroll
    for (int mi = 0; mi < 4; mi++)
        #pragma unroll
        for (int ni = 0; ni < 4; ni++)
            #pragma unroll
            for (int z = 0; z < 4; z++) acc[mi][ni][z] = 0.f;

    float4 a_pf[4];
    uint4  a_pfh[2];
    float4 b_pf[4];

    // ---- stage chunk 0 into buffer 0
    if (A_HALF) {
        #pragma unroll
        for (int t = 0; t < 2; t++)
            a_pfh[t] = *reinterpret_cast<const uint4*>(
                &Ah[(size_t)(brow + a_m0h + t * 64) * K + a_k8]);
        #pragma unroll
        for (int t = 0; t < 2; t++)
            *reinterpret_cast<uint4*>(&As[0][a_m0h + t * 64][a_k8]) = a_pfh[t];
    } else {
        #pragma unroll
        for (int t = 0; t < 4; t++)
            a_pf[t] = *reinterpret_cast<const float4*>(
                &Af[(size_t)(brow + a_m0 + t * 32) * K + a_k4]);
        #pragma unroll
        for (int t = 0; t < 4; t++) {
            __half2 h0 = __float22half2_rn(make_float2(a_pf[t].x, a_pf[t].y));
            __half2 h1 = __float22half2_rn(make_float2(a_pf[t].z, a_pf[t].w));
            *reinterpret_cast<__half2*>(&As[0][a_m0 + t * 32][a_k4 + 0]) = h0;
            *reinterpret_cast<__half2*>(&As[0][a_m0 + t * 32][a_k4 + 2]) = h1;
        }
    }
    #pragma unroll
    for (int t = 0; t < 4; t++)
        b_pf[t] = *reinterpret_cast<const float4*>(
            &B[(size_t)(b_k0 + t * 8) * N + bcol + b_n4]);
    #pragma unroll
    for (int t = 0; t < 4; t++) {
        __half2 g0 = __float22half2_rn(make_float2(b_pf[t].x, b_pf[t].y));
        __half2 g1 = __float22half2_rn(make_float2(b_pf[t].z, b_pf[t].w));
        *reinterpret_cast<__half2*>(&Bs[0][b_k0 + t * 8][b_n4 + 0]) = g0;
        *reinterpret_cast<__half2*>(&Bs[0][b_k0 + t * 8][b_n4 + 2]) = g1;
    }
    __syncthreads();

    int cur = 0;
    for (int kt = 0; kt < K; kt += 32) {
        const bool more = (kt + 32 < K);
        if (more) {
            if (A_HALF) {
                #pragma unroll
                for (int t = 0; t < 2; t++)
                    a_pfh[t] = *reinterpret_cast<const uint4*>(
                        &Ah[(size_t)(brow + a_m0h + t * 64) * K + kt + 32 + a_k8]);
            } else {
                #pragma unroll
                for (int t = 0; t < 4; t++)
                    a_pf[t] = *reinterpret_cast<const float4*>(
                        &Af[(size_t)(brow + a_m0 + t * 32) * K + kt + 32 + a_k4]);
            }
            #pragma unroll
            for (int t = 0; t < 4; t++)
                b_pf[t] = *reinterpret_cast<const float4*>(
                    &B[(size_t)(kt + 32 + b_k0 + t * 8) * N + bcol + b_n4]);
        }

        const u32 a_base = a_smem0 + (u32)cur * A_BUF;
        const u32 b_base = b_smem0 + (u32)cur * B_BUF;
        #pragma unroll
        for (int ks = 0; ks < 32; ks += 16) {
            u32 af[4][4];
            #pragma unroll
            for (int mi = 0; mi < 4; mi++) {
                int r = warp_m * 64 + mi * 16 + (lane & 15);
                int c = ks + ((lane >> 4) << 3);
                u32 addr = a_base + (u32)(r * 40 + c) * 2u;
                asm volatile(
                    "ldmatrix.sync.aligned.m8n8.x4.shared.b16 {%0,%1,%2,%3}, [%4];"
                    : "=r"(af[mi][0]), "=r"(af[mi][1]), "=r"(af[mi][2]), "=r"(af[mi][3])
                    : "r"(addr));
            }
            u32 bf[4][2];
            #pragma unroll
            for (int p = 0; p < 2; p++) {
                int r = ks + (lane & 15);
                int c = warp_n * 32 + p * 16 + ((lane >> 4) << 3);
                u32 addr = b_base + (u32)(r * 136 + c) * 2u;
                asm volatile(
                    "ldmatrix.sync.aligned.m8n8.x4.trans.shared.b16 {%0,%1,%2,%3}, [%4];"
                    : "=r"(bf[2*p][0]), "=r"(bf[2*p][1]),
                      "=r"(bf[2*p+1][0]), "=r"(bf[2*p+1][1])
                    : "r"(addr));
            }
            #pragma unroll
            for (int mi = 0; mi < 4; mi++)
                #pragma unroll
                for (int ni = 0; ni < 4; ni++) {
                    MMA16816(acc[mi][ni][0], acc[mi][ni][1],
                             acc[mi][ni][2], acc[mi][ni][3],
                             af[mi][0], af[mi][1], af[mi][2], af[mi][3],
                             bf[ni][0], bf[ni][1]);
                }
        }

        if (more) {
            const int nxt = cur ^ 1;
            if (A_HALF) {
                #pragma unroll
                for (int t = 0; t < 2; t++)
                    *reinterpret_cast<uint4*>(&As[nxt][a_m0h + t * 64][a_k8]) = a_pfh[t];
            } else {
                #pragma unroll
                for (int t = 0; t < 4; t++) {
                    __half2 h0 = __float22half2_rn(make_float2(a_pf[t].x, a_pf[t].y));
                    __half2 h1 = __float22half2_rn(make_float2(a_pf[t].z, a_pf[t].w));
                    *reinterpret_cast<__half2*>(&As[nxt][a_m0 + t * 32][a_k4 + 0]) = h0;
                    *reinterpret_cast<__half2*>(&As[nxt][a_m0 + t * 32][a_k4 + 2]) = h1;
                }
            }
            #pragma unroll
            for (int t = 0; t < 4; t++) {
                __half2 g0 = __float22half2_rn(make_float2(b_pf[t].x, b_pf[t].y));
                __half2 g1 = __float22half2_rn(make_float2(b_pf[t].z, b_pf[t].w));
                *reinterpret_cast<__half2*>(&Bs[nxt][b_k0 + t * 8][b_n4 + 0]) = g0;
                *reinterpret_cast<__half2*>(&Bs[nxt][b_k0 + t * 8][b_n4 + 2]) = g1;
            }
        }
        __syncthreads();
        cur ^= 1;
    }

    const int g = lane >> 2;
    const int t = lane & 3;

    if (ACT == 2) {
        #pragma unroll
        for (int mi = 0; mi < 4; mi++) {
            #pragma unroll
            for (int ni = 0; ni < 4; ni++) {
                const int c = warp_n * 32 + ni * 8 + (t << 1);
                float2 bb = *reinterpret_cast<const float2*>(&bias[c]);
                acc[mi][ni][0] += bb.x; acc[mi][ni][1] += bb.y;
                acc[mi][ni][2] += bb.x; acc[mi][ni][3] += bb.y;
            }
            float s0 = 0.f, q0 = 0.f, s1 = 0.f, q1 = 0.f;
            #pragma unroll
            for (int ni = 0; ni < 4; ni++) {
                s0 += acc[mi][ni][0] + acc[mi][ni][1];
                q0 += acc[mi][ni][0]*acc[mi][ni][0] + acc[mi][ni][1]*acc[mi][ni][1];
                s1 += acc[mi][ni][2] + acc[mi][ni][3];
                q1 += acc[mi][ni][2]*acc[mi][ni][2] + acc[mi][ni][3]*acc[mi][ni][3];
            }
            s0 += __shfl_xor_sync(0xffffffffu, s0, 1);
            s0 += __shfl_xor_sync(0xffffffffu, s0, 2);
            q0 += __shfl_xor_sync(0xffffffffu, q0, 1);
            q0 += __shfl_xor_sync(0xffffffffu, q0, 2);
            s1 += __shfl_xor_sync(0xffffffffu, s1, 1);
            s1 += __shfl_xor_sync(0xffffffffu, s1, 2);
            q1 += __shfl_xor_sync(0xffffffffu, q1, 1);
            q1 += __shfl_xor_sync(0xffffffffu, q1, 2);
            if (t == 0) {
                const int rl = warp_m * 64 + mi * 16 + g;
                red[rl][warp_n]     = make_float2(s0, q0);
                red[rl + 8][warp_n] = make_float2(s1, q1);
            }
        }
        __syncthreads();

        #pragma unroll
        for (int mi = 0; mi < 4; mi++) {
            const int rl0 = warp_m * 64 + mi * 16 + g;
            const int rl1 = rl0 + 8;
            float2 p;
            float s0 = 0.f, q0 = 0.f, s1 = 0.f, q1 = 0.f;
            #pragma unroll
            for (int w = 0; w < 4; w++) {
                p = red[rl0][w]; s0 += p.x; q0 += p.y;
                p = red[rl1][w]; s1 += p.x; q1 += p.y;
            }
            const float mu0 = s0 * (1.f/128.f);
            const float mu1 = s1 * (1.f/128.f);
            const float rs0 = rsqrtf(q0 * (1.f/128.f) - mu0*mu0 + 1e-5f);
            const float rs1 = rsqrtf(q1 * (1.f/128.f) - mu1*mu1 + 1e-5f);

            const size_t gr0 = (size_t)(brow + rl0) * 128;
            const size_t gr1 = (size_t)(brow + rl1) * 128;
            #pragma unroll
            for (int ni = 0; ni < 4; ni++) {
                const int c = warp_n * 32 + ni * 8 + (t << 1);
                float2 wv = *reinterpret_cast<const float2*>(&lnw[c]);
                float2 bv = *reinterpret_cast<const float2*>(&lnb[c]);
                float2 r0v = *reinterpret_cast<const float2*>(&res[gr0 + c]);
                float2 r1v = *reinterpret_cast<const float2*>(&res[gr1 + c]);
                float2 o0, o1;
                o0.x = r0v.x + (acc[mi][ni][0] - mu0) * rs0 * wv.x + bv.x;
                o0.y = r0v.y + (acc[mi][ni][1] - mu0) * rs0 * wv.y + bv.y;
                o1.x = r1v.x + (acc[mi][ni][2] - mu1) * rs1 * wv.x + bv.x;
                o1.y = r1v.y + (acc[mi][ni][3] - mu1) * rs1 * wv.y + bv.y;
                *reinterpret_cast<float2*>(&Cf[gr0 + c]) = o0;
                *reinterpret_cast<float2*>(&Cf[gr1 + c]) = o1;
            }
        }
        return;
    }

    #pragma unroll
    for (int mi = 0; mi < 4; mi++) {
        #pragma unroll
        for (int ni = 0; ni < 4; ni++) {
            const int r0 = brow + warp_m * 64 + mi * 16 + g;
            const int c  = bcol + warp_n * 32 + ni * 8 + (t << 1);
            float2 bb = *reinterpret_cast<const float2*>(&bias[c]);
            float2 v0, v1;
            v0.x = acc[mi][ni][0] + bb.x; v0.y = acc[mi][ni][1] + bb.y;
            v1.x = acc[mi][ni][2] + bb.x; v1.y = acc[mi][ni][3] + bb.y;
            if (ACT == 1) {
                v0.x *= normcdff(v0.x); v0.y *= normcdff(v0.y);
                v1.x *= normcdff(v1.x); v1.y *= normcdff(v1.y);
            }
            if (C_HALF) {
                *reinterpret_cast<__half2*>(&Ch[(size_t)r0 * N + c]) =
                    __float22half2_rn(v0);
                *reinterpret_cast<__half2*>(&Ch[(size_t)(r0 + 8) * N + c]) =
                    __float22half2_rn(v1);
            } else {
                *reinterpret_cast<float2*>(&Cf[(size_t)r0 * N + c])       = v0;
                *reinterpret_cast<float2*>(&Cf[(size_t)(r0 + 8) * N + c]) = v1;
            }
        }
    }
}

// ---------------------------------------------------------------------------
// Shifted bias in mma C-fragment layout, fp32:
// stored = (b(i,j) - scale_hd) * log2e.
// ---------------------------------------------------------------------------
__global__ void biasf_kernel(const int* __restrict__ rpi,
                             const float* __restrict__ table,
                             const float* __restrict__ logit_scale,
                             float4* __restrict__ biasF)
{
    const int unit = blockIdx.x * 8 + (threadIdx.x >> 5);
    const int qb = unit >> 5;
    const int jt = unit & 31;
    const int hd = blockIdx.y;
    const int lane = threadIdx.x & 31;
    const int g = lane >> 2, t = lane & 3;
    const int i0 = qb * 16, j0 = jt * 8;

    const float shift = __expf(fminf(logit_scale[hd], 4.6051702f)) * LOG2E;

    float4 r;
    r.x = table[rpi[(i0 + g)     * NTOK + j0 + 2*t    ] * NH + hd] * LOG2E - shift;
    r.y = table[rpi[(i0 + g)     * NTOK + j0 + 2*t + 1] * NH + hd] * LOG2E - shift;
    r.z = table[rpi[(i0 + g + 8) * NTOK + j0 + 2*t    ] * NH + hd] * LOG2E - shift;
    r.w = table[rpi[(i0 + g + 8) * NTOK + j0 + 2*t + 1] * NH + hd] * LOG2E - shift;
    biasF[((size_t)(hd * 16 + qb) * 32 + jt) * 32 + lane] = r;
}

// ---------------------------------------------------------------------------
// Paired tensor-core window attention; fp16x2 exp2 on shifted logits;
// softmax denominator via MMA against constant ones-B.
// smem: Kh [256][24] + Vt [16][264] = 20.4 KB.
// ---------------------------------------------------------------------------
#define SKH  0
#define SVTH (256*24)
#define ATTN_SMEM_HALFS (256*24 + 16*264)
#define ONE2 0x3C003C00u

__global__ __launch_bounds__(128, 4) void attn_tc_kernel(
    const __half* __restrict__ qkv, const float4* __restrict__ biasF,
    const float* __restrict__ logit_scale, __half* __restrict__ attn_out)
{
    __shared__ __half sm[ATTN_SMEM_HALFS];

    const int wi = blockIdx.x;
    const int hd = blockIdx.y;
    const int tid = threadIdx.x;

    const int bimg = wi / 144;
    const int wrem = wi % 144;
    const int wr = wrem / WPR, wc = wrem % WPR;
    const int rowbase = bimg * (IMG * IMG) + (wr * 16) * IMG + wc * 16;

    const float scale = __expf(fminf(logit_scale[hd], 4.6051702f));
    const float qmul  = scale * LOG2E;

    for (int tok = tid; tok < NTOK; tok += 128) {
        const int m = rowbase + (tok >> 4) * IMG + (tok & 15);
        const __half* base = qkv + (size_t)m * 384 + hd * HD;

        uint4 kraw0 = *reinterpret_cast<const uint4*>(base + 128);
        uint4 kraw1 = *reinterpret_cast<const uint4*>(base + 136);
        uint4 vraw0 = *reinterpret_cast<const uint4*>(base + 256);
        uint4 vraw1 = *reinterpret_cast<const uint4*>(base + 264);

        float kf[16];
        {
            const __half2* k2a = reinterpret_cast<const __half2*>(&kraw0);
            const __half2* k2b = reinterpret_cast<const __half2*>(&kraw1);
            #pragma unroll
            for (int z = 0; z < 4; z++) {
                float2 f = __half22float2(k2a[z]);
                kf[2*z] = f.x; kf[2*z+1] = f.y;
                f = __half22float2(k2b[z]);
                kf[8+2*z] = f.x; kf[8+2*z+1] = f.y;
            }
        }
        float ks = 0.f;
        #pragma unroll
        for (int z = 0; z < 16; z++) ks += kf[z] * kf[z];
        const float kr = 1.f / fmaxf(sqrtf(ks), 1e-12f);
        #pragma unroll
        for (int z = 0; z < 16; z++)
            sm[SKH + tok*24 + z] = __float2half_rn(kf[z] * kr);

        const __half* vh = reinterpret_cast<const __half*>(&vraw0);
        #pragma unroll
        for (int z = 0; z < 8; z++) sm[SVTH + z*264 + tok] = vh[z];
        vh = reinterpret_cast<const __half*>(&vraw1);
        #pragma unroll
        for (int z = 0; z < 8; z++) sm[SVTH + (8+z)*264 + tok] = vh[z];
    }
    __syncthreads();

    const int warp = tid >> 5;
    const int lane = tid & 31;
    const int g = lane >> 2;
    const int t = lane & 3;

    for (int qp = 0; qp < 2; qp++) {
        const int qbA = warp * 4 + qp * 2;
        const int qbB = qbA + 1;

        int mA0, mA1, mB0, mB1;
        u32 qaA[4], qaB[4];
        {
            const int iA = qbA * 16, iB = qbB * 16;
            const int rA0 = iA + g, rA1 = iA + g + 8;
            const int rB0 = iB + g, rB1 = iB + g + 8;
            mA0 = rowbase + (rA0 >> 4) * IMG + (rA0 & 15);
            mA1 = rowbase + (rA1 >> 4) * IMG + (rA1 & 15);
            mB0 = rowbase + (rB0 >> 4) * IMG + (rB0 & 15);
            mB1 = rowbase + (rB1 >> 4) * IMG + (rB1 & 15);

            const __half* pA0 = qkv + (size_t)mA0 * 384 + hd * HD;
            const __half* pA1 = qkv + (size_t)mA1 * 384 + hd * HD;
            const __half* pB0 = qkv + (size_t)mB0 * 384 + hd * HD;
            const __half* pB1 = qkv + (size_t)mB1 * 384 + hd * HD;

            float2 aA00 = __half22float2(*reinterpret_cast<const __half2*>(pA0 + 2*t));
            float2 aA01 = __half22float2(*reinterpret_cast<const __half2*>(pA0 + 2*t + 8));
            float2 aA10 = __half22float2(*reinterpret_cast<const __half2*>(pA1 + 2*t));
            float2 aA11 = __half22float2(*reinterpret_cast<const __half2*>(pA1 + 2*t + 8));
            float2 aB00 = __half22float2(*reinterpret_cast<const __half2*>(pB0 + 2*t));
            float2 aB01 = __half22float2(*reinterpret_cast<const __half2*>(pB0 + 2*t + 8));
            float2 aB10 = __half22float2(*reinterpret_cast<const __half2*>(pB1 + 2*t));
            float2 aB11 = __half22float2(*reinterpret_cast<const __half2*>(pB1 + 2*t + 8));

            float sA0 = aA00.x*aA00.x + aA00.y*aA00.y + aA01.x*aA01.x + aA01.y*aA01.y;
            float sA1 = aA10.x*aA10.x + aA10.y*aA10.y + aA11.x*aA11.x + aA11.y*aA11.y;
            float sB0 = aB00.x*aB00.x + aB00.y*aB00.y + aB01.x*aB01.x + aB01.y*aB01.y;
            float sB1 = aB10.x*aB10.x + aB10.y*aB10.y + aB11.x*aB11.x + aB11.y*aB11.y;
            sA0 += __shfl_xor_sync(0xffffffffu, sA0, 1);
            sA0 += __shfl_xor_sync(0xffffffffu, sA0, 2);
            sA1 += __shfl_xor_sync(0xffffffffu, sA1, 1);
            sA1 += __shfl_xor_sync(0xffffffffu, sA1, 2);
            sB0 += __shfl_xor_sync(0xffffffffu, sB0, 1);
            sB0 += __shfl_xor_sync(0xffffffffu, sB0, 2);
            sB1 += __shfl_xor_sync(0xffffffffu, sB1, 1);
            sB1 += __shfl_xor_sync(0xffffffffu, sB1, 2);
            const float qrA0 = qmul / fmaxf(sqrtf(sA0), 1e-12f);
            const float qrA1 = qmul / fmaxf(sqrtf(sA1), 1e-12f);
            const float qrB0 = qmul / fmaxf(sqrtf(sB0), 1e-12f);
            const float qrB1 = qmul / fmaxf(sqrtf(sB1), 1e-12f);

            __half2 h;
            h = __floats2half2_rn(aA00.x * qrA0, aA00.y * qrA0); qaA[0] = *reinterpret_cast<u32*>(&h);
            h = __floats2half2_rn(aA10.x * qrA1, aA10.y * qrA1); qaA[1] = *reinterpret_cast<u32*>(&h);
            h = __floats2half2_rn(aA01.x * qrA0, aA01.y * qrA0); qaA[2] = *reinterpret_cast<u32*>(&h);
            h = __floats2half2_rn(aA11.x * qrA1, aA11.y * qrA1); qaA[3] = *reinterpret_cast<u32*>(&h);
            h = __floats2half2_rn(aB00.x * qrB0, aB00.y * qrB0); qaB[0] = *reinterpret_cast<u32*>(&h);
            h = __floats2half2_rn(aB10.x * qrB1, aB10.y * qrB1); qaB[1] = *reinterpret_cast<u32*>(&h);
            h = __floats2half2_rn(aB01.x * qrB0, aB01.y * qrB0); qaB[2] = *reinterpret_cast<u32*>(&h);
            h = __floats2half2_rn(aB11.x * qrB1, aB11.y * qrB1); qaB[3] = *reinterpret_cast<u32*>(&h);
        }

        float oA0[4] = {0,0,0,0}, oA1[4] = {0,0,0,0};
        float oB0[4] = {0,0,0,0}, oB1[4] = {0,0,0,0};
        float lA[4] = {0,0,0,0}, lB[4] = {0,0,0,0};

        const float4* bpA = biasF + ((size_t)(hd * 16 + qbA) * 32) * 32 + lane;
        const float4* bpB = biasF + ((size_t)(hd * 16 + qbB) * 32) * 32 + lane;

        #pragma unroll 2
        for (int jp = 0; jp < 16; jp++) {
            const int j0a = (2 * jp) * 8;
            const int j0b = (2 * jp + 1) * 8;
            float4 bA0 = __ldg(&bpA[(2 * jp) * 32]);
            float4 bA1 = __ldg(&bpA[(2 * jp + 1) * 32]);
            float4 bB0 = __ldg(&bpB[(2 * jp) * 32]);
            float4 bB1 = __ldg(&bpB[(2 * jp + 1) * 32]);

            u32 kh0 = *reinterpret_cast<u32*>(&sm[SKH + (j0a+g)*24 + 2*t]);
            u32 kh1 = *reinterpret_cast<u32*>(&sm[SKH + (j0a+g)*24 + 2*t + 8]);
            u32 mh0 = *reinterpret_cast<u32*>(&sm[SKH + (j0b+g)*24 + 2*t]);
            u32 mh1 = *reinterpret_cast<u32*>(&sm[SKH + (j0b+g)*24 + 2*t + 8]);

            float sAa0=0,sAa1=0,sAa2=0,sAa3=0, sAb0=0,sAb1=0,sAb2=0,sAb3=0;
            MMA16816(sAa0,sAa1,sAa2,sAa3, qaA[0],qaA[1],qaA[2],qaA[3], kh0,kh1);
            MMA16816(sAb0,sAb1,sAb2,sAb3, qaA[0],qaA[1],qaA[2],qaA[3], mh0,mh1);
            float sBa0=0,sBa1=0,sBa2=0,sBa3=0, sBb0=0,sBb1=0,sBb2=0,sBb3=0;
            MMA16816(sBa0,sBa1,sBa2,sBa3, qaB[0],qaB[1],qaB[2],qaB[3], kh0,kh1);
            MMA16816(sBb0,sBb1,sBb2,sBb3, qaB[0],qaB[1],qaB[2],qaB[3], mh0,mh1);

            // p = exp2(s + b_shifted) in fp16x2; fragments ready for PV MMAs
            u32 aA0c = h2ex2(__floats2half2_rn(sAa0 + bA0.x, sAa1 + bA0.y));
            u32 aA1c = h2ex2(__floats2half2_rn(sAa2 + bA0.z, sAa3 + bA0.w));
            u32 aA2c = h2ex2(__floats2half2_rn(sAb0 + bA1.x, sAb1 + bA1.y));
            u32 aA3c = h2ex2(__floats2half2_rn(sAb2 + bA1.z, sAb3 + bA1.w));
            u32 aB0c = h2ex2(__floats2half2_rn(sBa0 + bB0.x, sBa1 + bB0.y));
            u32 aB1c = h2ex2(__floats2half2_rn(sBa2 + bB0.z, sBa3 + bB0.w));
            u32 aB2c = h2ex2(__floats2half2_rn(sBb0 + bB1.x, sBb1 + bB1.y));
            u32 aB3c = h2ex2(__floats2half2_rn(sBb2 + bB1.z, sBb3 + bB1.w));

            const int jb = jp * 16;
            u32 vh0 = *reinterpret_cast<u32*>(&sm[SVTH + g*264 + jb + 2*t]);
            u32 vh1 = *reinterpret_cast<u32*>(&sm[SVTH + g*264 + jb + 2*t + 8]);
            u32 wh0 = *reinterpret_cast<u32*>(&sm[SVTH + (8+g)*264 + jb + 2*t]);
            u32 wh1 = *reinterpret_cast<u32*>(&sm[SVTH + (8+g)*264 + jb + 2*t + 8]);

            MMA16816(oA0[0],oA0[1],oA0[2],oA0[3], aA0c,aA1c,aA2c,aA3c, vh0,vh1);
            MMA16816(oA1[0],oA1[1],oA1[2],oA1[3], aA0c,aA1c,aA2c,aA3c, wh0,wh1);
            MMA16816(lA[0],lA[1],lA[2],lA[3],     aA0c,aA1c,aA2c,aA3c, ONE2,ONE2);
            MMA16816(oB0[0],oB0[1],oB0[2],oB0[3], aB0c,aB1c,aB2c,aB3c, vh0,vh1);
            MMA16816(oB1[0],oB1[1],oB1[2],oB1[3], aB0c,aB1c,aB2c,aB3c, wh0,wh1);
            MMA16816(lB[0],lB[1],lB[2],lB[3],     aB0c,aB1c,aB2c,aB3c, ONE2,ONE2);
        }

        const float iA0 = 1.f / lA[0], iA1 = 1.f / lA[2];
        const float iB0 = 1.f / lB[0], iB1 = 1.f / lB[2];

        const int col = hd * HD + 2 * t;
        *reinterpret_cast<__half2*>(&attn_out[(size_t)mA0 * C_DIM + col]) =
            __floats2half2_rn(oA0[0] * iA0, oA0[1] * iA0);
        *reinterpret_cast<__half2*>(&attn_out[(size_t)mA1 * C_DIM + col]) =
            __floats2half2_rn(oA0[2] * iA1, oA0[3] * iA1);
        *reinterpret_cast<__half2*>(&attn_out[(size_t)mA0 * C_DIM + col + 8]) =
            __floats2half2_rn(oA1[0] * iA0, oA1[1] * iA0);
        *reinterpret_cast<__half2*>(&attn_out[(size_t)mA1 * C_DIM + col + 8]) =
            __floats2half2_rn(oA1[2] * iA1, oA1[3] * iA1);
        *reinterpret_cast<__half2*>(&attn_out[(size_t)mB0 * C_DIM + col]) =
            __floats2half2_rn(oB0[0] * iB0, oB0[1] * iB0);
        *reinterpret_cast<__half2*>(&attn_out[(size_t)mB1 * C_DIM + col]) =
            __floats2half2_rn(oB0[2] * iB1, oB0[3] * iB1);
        *reinterpret_cast<__half2*>(&attn_out[(size_t)mB0 * C_DIM + col + 8]) =
            __floats2half2_rn(oB1[0] * iB0, oB1[1] * iB0);
        *reinterpret_cast<__half2*>(&attn_out[(size_t)mB1 * C_DIM + col + 8]) =
            __floats2half2_rn(oB1[2] * iB1, oB1[3] * iB1);
    }
}

// ---------------------------------------------------------------------------
extern "C" void kernel_launch(void* const* d_in, const int* in_sizes, int n_in,
                              void* d_out, int out_size)
{
    const float* x           = (const float*)d_in[0];
    const float* qkv_w       = (const float*)d_in[1];
    const float* qkv_b       = (const float*)d_in[2];
    const float* proj_w      = (const float*)d_in[3];
    const float* proj_b      = (const float*)d_in[4];
    const float* logit_scale = (const float*)d_in[5];
    const float* rpb_table   = (const float*)d_in[6];
    const float* n1w         = (const float*)d_in[7];
    const float* n1b         = (const float*)d_in[8];
    const float* n2w         = (const float*)d_in[9];
    const float* n2b         = (const float*)d_in[10];
    const float* fc1_w       = (const float*)d_in[11];
    const float* fc1_b       = (const float*)d_in[12];
    const float* fc2_w       = (const float*)d_in[13];
    const float* fc2_b       = (const float*)d_in[14];
    const int*   rpi         = (const int*)d_in[17];
    float* out = (float*)d_out;

    float *p_x1;
    __half *p_qkvh, *p_attnh, *p_hidh;
    float4 *p_biasF;
    cudaGetSymbolAddress((void**)&p_qkvh,  g_qkvh);
    cudaGetSymbolAddress((void**)&p_biasF, g_biasF);
    cudaGetSymbolAddress((void**)&p_attnh, g_attnh);
    cudaGetSymbolAddress((void**)&p_x1,    g_x1);
    cudaGetSymbolAddress((void**)&p_hidh,  g_hidh);

    // 1) shifted bias fragments (fp32)
    biasf_kernel<<<dim3(64, NH), 256>>>(rpi, rpb_table, logit_scale, p_biasF);

    // 2) QKV: fp32 A, fp16 C
    hgemm_kernel<false,true,0><<<dim3(384/128, M_TOK/128), 256>>>(
        x, qkv_w, qkv_b, p_qkvh, M_TOK, 384, 128, nullptr, nullptr, nullptr);

    // 3) paired tensor-core window attention (fp16x2 exp, MMA row sums)
    attn_tc_kernel<<<dim3(NWIN, NH), 128>>>(p_qkvh, p_biasF, logit_scale, p_attnh);

    // 4) proj + fused LN + residual
    hgemm_kernel<true,false,2><<<dim3(1, M_TOK/128), 256>>>(
        p_attnh, proj_w, proj_b, p_x1, M_TOK, 128, 128, x, n1w, n1b);

    // 5) fc1 + GELU
    hgemm_kernel<false,true,1><<<dim3(256/128, M_TOK/128), 256>>>(
        p_x1, fc1_w, fc1_b, p_hidh, M_TOK, 256, 128, nullptr, nullptr, nullptr);

    // 6) fc2 + fused LN + residual
    hgemm_kernel<true,false,2><<<dim3(1, M_TOK/128), 256>>>(
        p_hidh, fc2_w, fc2_b, out, M_TOK, 128, 256, p_x1, n2w, n2b);
}